// round 1
// baseline (speedup 1.0000x reference)
#include <cuda_runtime.h>
#include <cstdint>
#include <math.h>

#define NB   4
#define NN   4096
#define CC   256
#define NH   8
#define DH   32
#define KNN  16
#define HDIM 256
#define TOT  (NB*NN)          // 16384 nodes total

// ---------------- scratch (static device globals; no allocation) ----------------
__device__ float g_q [(size_t)TOT*HDIM];
__device__ float g_k [(size_t)TOT*HDIM];
__device__ float g_v [(size_t)TOT*HDIM];
__device__ float g_sq[TOT];
__device__ float g_d2[(size_t)NB*NN*NN];        // 268 MB distance matrix
__device__ int   g_nbr[(size_t)TOT*KNN];

// ---------------- squared norms ----------------
__global__ void norms_kernel(const float* __restrict__ x) {
    int row  = blockIdx.x * 8 + (threadIdx.x >> 5);
    int lane = threadIdx.x & 31;
    const float4* xr = reinterpret_cast<const float4*>(x + (size_t)row * CC);
    float s = 0.f;
#pragma unroll
    for (int c = 0; c < 2; c++) {
        float4 v = xr[lane + 32*c];
        s += v.x*v.x + v.y*v.y + v.z*v.z + v.w*v.w;
    }
#pragma unroll
    for (int o = 16; o; o >>= 1) s += __shfl_xor_sync(0xffffffffu, s, o);
    if (lane == 0) g_sq[row] = s;
}

// ---------------- fused QKV GEMM: out = x @ W + b, blockIdx.z selects q/k/v ----------------
__global__ __launch_bounds__(256, 2)
void qkv_kernel(const float* __restrict__ x,
                const float* __restrict__ Wq, const float* __restrict__ bq,
                const float* __restrict__ Wk, const float* __restrict__ bk,
                const float* __restrict__ Wv, const float* __restrict__ bv) {
    __shared__ float As[32][128];
    __shared__ float Bs[32][128];

    const float* W; const float* bias; float* outp;
    if (blockIdx.z == 0)      { W = Wq; bias = bq; outp = g_q; }
    else if (blockIdx.z == 1) { W = Wk; bias = bk; outp = g_k; }
    else                      { W = Wv; bias = bv; outp = g_v; }

    int tid = threadIdx.x;
    int tx = tid & 15, ty = tid >> 4;
    int m0 = blockIdx.y * 128, n0 = blockIdx.x * 128;

    float acc[8][8];
#pragma unroll
    for (int i = 0; i < 8; i++)
#pragma unroll
        for (int j = 0; j < 8; j++) acc[i][j] = 0.f;

    for (int k0 = 0; k0 < CC; k0 += 32) {
#pragma unroll
        for (int p = 0; p < 4; p++) {
            int r = p*32 + (tid >> 3), c4 = tid & 7;
            float4 v = *reinterpret_cast<const float4*>(x + (size_t)(m0 + r)*CC + k0 + c4*4);
            As[c4*4+0][r] = v.x; As[c4*4+1][r] = v.y;
            As[c4*4+2][r] = v.z; As[c4*4+3][r] = v.w;
        }
#pragma unroll
        for (int p = 0; p < 4; p++) {
            int r = p*8 + (tid >> 5), c4 = tid & 31;
            *reinterpret_cast<float4*>(&Bs[r][c4*4]) =
                *reinterpret_cast<const float4*>(W + (size_t)(k0 + r)*HDIM + n0 + c4*4);
        }
        __syncthreads();
#pragma unroll
        for (int k = 0; k < 32; k++) {
            float a[8], b[8];
            *(float4*)(a)   = *(float4*)(&As[k][ty*8]);
            *(float4*)(a+4) = *(float4*)(&As[k][ty*8+4]);
            *(float4*)(b)   = *(float4*)(&Bs[k][tx*8]);
            *(float4*)(b+4) = *(float4*)(&Bs[k][tx*8+4]);
#pragma unroll
            for (int i = 0; i < 8; i++)
#pragma unroll
                for (int j = 0; j < 8; j++) acc[i][j] += a[i]*b[j];
        }
        __syncthreads();
    }
#pragma unroll
    for (int i = 0; i < 8; i++) {
        int m = m0 + ty*8 + i;
#pragma unroll
        for (int j4 = 0; j4 < 2; j4++) {
            int n = n0 + tx*8 + j4*4;
            float4 o;
            o.x = acc[i][j4*4+0] + bias[n+0];
            o.y = acc[i][j4*4+1] + bias[n+1];
            o.z = acc[i][j4*4+2] + bias[n+2];
            o.w = acc[i][j4*4+3] + bias[n+3];
            *reinterpret_cast<float4*>(outp + (size_t)m*HDIM + n) = o;
        }
    }
}

// ---------------- Gram / distance matrix (symmetric, bx >= by only) ----------------
__global__ __launch_bounds__(256, 2)
void gram_kernel(const float* __restrict__ x) {
    int bx = blockIdx.x, by = blockIdx.y, bz = blockIdx.z;
    if (bx < by) return;

    __shared__ float As[32][128];
    __shared__ float Bs[32][128];
    const float* xb = x + (size_t)bz * NN * CC;

    int tid = threadIdx.x;
    int tx = tid & 15, ty = tid >> 4;
    int i0 = by * 128, j0 = bx * 128;

    float acc[8][8];
#pragma unroll
    for (int i = 0; i < 8; i++)
#pragma unroll
        for (int j = 0; j < 8; j++) acc[i][j] = 0.f;

    for (int k0 = 0; k0 < CC; k0 += 32) {
#pragma unroll
        for (int p = 0; p < 4; p++) {
            int r = p*32 + (tid >> 3), c4 = tid & 7;
            float4 v = *reinterpret_cast<const float4*>(xb + (size_t)(i0 + r)*CC + k0 + c4*4);
            As[c4*4+0][r] = v.x; As[c4*4+1][r] = v.y;
            As[c4*4+2][r] = v.z; As[c4*4+3][r] = v.w;
            float4 w = *reinterpret_cast<const float4*>(xb + (size_t)(j0 + r)*CC + k0 + c4*4);
            Bs[c4*4+0][r] = w.x; Bs[c4*4+1][r] = w.y;
            Bs[c4*4+2][r] = w.z; Bs[c4*4+3][r] = w.w;
        }
        __syncthreads();
#pragma unroll
        for (int k = 0; k < 32; k++) {
            float a[8], b[8];
            *(float4*)(a)   = *(float4*)(&As[k][ty*8]);
            *(float4*)(a+4) = *(float4*)(&As[k][ty*8+4]);
            *(float4*)(b)   = *(float4*)(&Bs[k][tx*8]);
            *(float4*)(b+4) = *(float4*)(&Bs[k][tx*8+4]);
#pragma unroll
            for (int i = 0; i < 8; i++)
#pragma unroll
                for (int j = 0; j < 8; j++) acc[i][j] += a[i]*b[j];
        }
        __syncthreads();
    }

    const float* sqb = g_sq + bz * NN;
    float sqi[8], sqj[8];
#pragma unroll
    for (int i = 0; i < 8; i++) sqi[i] = sqb[i0 + ty*8 + i];
#pragma unroll
    for (int j = 0; j < 8; j++) sqj[j] = sqb[j0 + tx*8 + j];

    float* d2b = g_d2 + (size_t)bz * NN * NN;
    const float FINF = __int_as_float(0x7f800000);

#pragma unroll
    for (int i = 0; i < 8; i++) {
        int gi = i0 + ty*8 + i;
#pragma unroll
        for (int j4 = 0; j4 < 2; j4++) {
            int gj = j0 + tx*8 + j4*4;
            float d0 = sqi[i] + sqj[j4*4+0] - 2.f*acc[i][j4*4+0];
            float d1 = sqi[i] + sqj[j4*4+1] - 2.f*acc[i][j4*4+1];
            float d2v = sqi[i] + sqj[j4*4+2] - 2.f*acc[i][j4*4+2];
            float d3 = sqi[i] + sqj[j4*4+3] - 2.f*acc[i][j4*4+3];
            if (gi == gj+0) d0 = FINF;
            if (gi == gj+1) d1 = FINF;
            if (gi == gj+2) d2v = FINF;
            if (gi == gj+3) d3 = FINF;
            *reinterpret_cast<float4*>(d2b + (size_t)gi*NN + gj) = make_float4(d0, d1, d2v, d3);
        }
    }
    if (bx != by) {  // mirror tile (no diagonal here)
#pragma unroll
        for (int j = 0; j < 8; j++) {
            int gj = j0 + tx*8 + j;
#pragma unroll
            for (int i4 = 0; i4 < 2; i4++) {
                int gi = i0 + ty*8 + i4*4;
                float t0 = sqi[i4*4+0] + sqj[j] - 2.f*acc[i4*4+0][j];
                float t1 = sqi[i4*4+1] + sqj[j] - 2.f*acc[i4*4+1][j];
                float t2 = sqi[i4*4+2] + sqj[j] - 2.f*acc[i4*4+2][j];
                float t3 = sqi[i4*4+3] + sqj[j] - 2.f*acc[i4*4+3][j];
                *reinterpret_cast<float4*>(d2b + (size_t)gj*NN + gi) = make_float4(t0, t1, t2, t3);
            }
        }
    }
}

// ---------------- top-16 smallest per row (one warp / row) ----------------
__global__ void topk_kernel() {
    int row  = (blockIdx.x * blockDim.x + threadIdx.x) >> 5;   // 0..TOT-1
    int lane = threadIdx.x & 31;
    const float4* rp = reinterpret_cast<const float4*>(g_d2 + (size_t)row * NN);
    const float FINF = __int_as_float(0x7f800000);

    // per-lane sorted-descending top-16 (best[0] = current worst). Static indexing only.
    float best[KNN]; int bidx[KNN];
#pragma unroll
    for (int t = 0; t < KNN; t++) { best[t] = FINF; bidx[t] = -1; }

    for (int it = 0; it < NN/128; it++) {
        float4 v = rp[it*32 + lane];
        int jb = (it*32 + lane) * 4;
        float dv[4] = {v.x, v.y, v.z, v.w};
#pragma unroll
        for (int c = 0; c < 4; c++) {
            float d = dv[c];
            if (d < best[0]) {
                best[0] = d; bidx[0] = jb + c;
#pragma unroll
                for (int t = 0; t < KNN-1; t++) {
                    if (best[t] < best[t+1]) {
                        float tv = best[t]; best[t] = best[t+1]; best[t+1] = tv;
                        int ti = bidx[t]; bidx[t] = bidx[t+1]; bidx[t+1] = ti;
                    }
                }
            }
        }
    }
    // warp merge: 16 extraction rounds; (dist,idx) packed key -> jax-stable tie-break
    for (int r = 0; r < KNN; r++) {
        unsigned long long key =
            ((unsigned long long)__float_as_uint(best[KNN-1]) << 32) | (unsigned)bidx[KNN-1];
        unsigned long long wk = key;
#pragma unroll
        for (int o = 16; o; o >>= 1) {
            unsigned long long other = __shfl_xor_sync(0xffffffffu, wk, o);
            if (other < wk) wk = other;
        }
        if (key == wk) {  // winner: consume min, shift array down
#pragma unroll
            for (int t = KNN-1; t > 0; t--) { best[t] = best[t-1]; bidx[t] = bidx[t-1]; }
            best[0] = FINF; bidx[0] = -1;
        }
        if (lane == 0) g_nbr[(size_t)row*KNN + r] = (int)(wk & 0xffffffffu);
    }
}

// ---------------- sparse attention: one warp per node, loop heads ----------------
__global__ void attn_kernel(float* __restrict__ out) {
    int node = (blockIdx.x * blockDim.x + threadIdx.x) >> 5;   // 0..TOT-1
    int lane = threadIdx.x & 31;
    int b = node >> 12;                                        // node / NN
    size_t base  = (size_t)node * HDIM;
    size_t bbase = (size_t)b * NN * HDIM;
    int nbr_l = g_nbr[(size_t)node*KNN + (lane & 15)];
    const float scale = 0.17677669529663687f;                  // 1/sqrt(32)
    const float NINF = -__int_as_float(0x7f800000);

    for (int h = 0; h < NH; h++) {
        int off = h*DH + lane;                                 // DH == 32 == warp
        float qd = g_q[base + off];
        float sc = 0.f;
#pragma unroll
        for (int kk = 0; kk < KNN; kk++) {
            int nb = __shfl_sync(0xffffffffu, nbr_l, kk);
            float p = qd * g_k[bbase + (size_t)nb*HDIM + off];
#pragma unroll
            for (int o = 16; o; o >>= 1) p += __shfl_xor_sync(0xffffffffu, p, o);
            if (lane == kk) sc = p * scale;
        }
        float m = (lane < 16) ? sc : NINF;
#pragma unroll
        for (int o = 16; o; o >>= 1) m = fmaxf(m, __shfl_xor_sync(0xffffffffu, m, o));
        float e = (lane < 16) ? expf(sc - m) : 0.f;
        float s = e;
#pragma unroll
        for (int o = 16; o; o >>= 1) s += __shfl_xor_sync(0xffffffffu, s, o);
        float alpha = e / s;
        float acc = 0.f;
#pragma unroll
        for (int kk = 0; kk < KNN; kk++) {
            float a = __shfl_sync(0xffffffffu, alpha, kk);
            int nb  = __shfl_sync(0xffffffffu, nbr_l, kk);
            acc += a * g_v[bbase + (size_t)nb*HDIM + off];
        }
        out[base + off] = acc;
    }
}

// ---------------- launch ----------------
extern "C" void kernel_launch(void* const* d_in, const int* in_sizes, int n_in,
                              void* d_out, int out_size) {
    const float* x  = (const float*)d_in[0];
    const float* Wq = (const float*)d_in[1];
    const float* bq = (const float*)d_in[2];
    const float* Wk = (const float*)d_in[3];
    const float* bk = (const float*)d_in[4];
    const float* Wv = (const float*)d_in[5];
    const float* bv = (const float*)d_in[6];
    float* out = (float*)d_out;

    norms_kernel<<<TOT/8, 256>>>(x);
    gram_kernel<<<dim3(NN/128, NN/128, NB), 256>>>(x);
    topk_kernel<<<TOT/8, 256>>>();
    qkv_kernel<<<dim3(HDIM/128, TOT/128, 3), 256>>>(x, Wq, bq, Wk, bk, Wv, bv);
    attn_kernel<<<TOT/8, 256>>>(out);
}

// round 4
// speedup vs baseline: 1.0104x; 1.0104x over previous
#include <cuda_runtime.h>
#include <cstdint>
#include <math.h>

#define NB   4
#define NN   4096
#define CC   256
#define NH   8
#define DH   32
#define KNN  16
#define CAND 20
#define HDIM 256
#define TOT  (NB*NN)          // 16384 nodes total

// ---------------- scratch (static device globals; no allocation) ----------------
__device__ float g_q [(size_t)TOT*HDIM];
__device__ float g_k [(size_t)TOT*HDIM];
__device__ float g_v [(size_t)TOT*HDIM];
__device__ float g_sq[TOT];
__device__ float g_d2[(size_t)NB*NN*NN];        // 268 MB distance matrix
__device__ float g_xa[(size_t)TOT*512];         // A-fragment layout hi|lo, 32 MB
__device__ float g_xb[(size_t)TOT*512];         // B-fragment layout hi|lo, 32 MB
__device__ int   g_nbr[(size_t)TOT*KNN];

// ================= helpers =================
__device__ __forceinline__ uint32_t smem_u32(const void* p) {
    uint32_t a;
    asm("{ .reg .u64 t; cvta.to.shared.u64 t, %1; cvt.u32.u64 %0, t; }" : "=r"(a) : "l"(p));
    return a;
}
#define CP_ASYNC16(saddr, gptr) \
    asm volatile("cp.async.cg.shared.global [%0], [%1], 16;" \
                 :: "r"((uint32_t)(saddr)), "l"(gptr) : "memory")
#define CP_COMMIT() asm volatile("cp.async.commit_group;" ::: "memory")
#define CP_WAIT(n)  asm volatile("cp.async.wait_group %0;" :: "n"(n) : "memory")

// mma.sync m16n8k8 tf32 (compute_80+, no 'a'-arch features)
#define MMA_TF32(c, a, b) \
    asm volatile("mma.sync.aligned.m16n8k8.row.col.f32.tf32.tf32.f32 " \
        "{%0,%1,%2,%3}, {%4,%5,%6,%7}, {%8,%9}, {%0,%1,%2,%3};" \
        : "+f"((c)[0]), "+f"((c)[1]), "+f"((c)[2]), "+f"((c)[3]) \
        : "r"((a).x), "r"((a).y), "r"((a).z), "r"((a).w), "r"((b).x), "r"((b).y))

__device__ __forceinline__ float tf32r(float v) {
    uint32_t u; asm("cvt.rna.tf32.f32 %0, %1;" : "=r"(u) : "f"(v));
    return __uint_as_float(u);
}

// ---------------- decomp: x -> tf32 hi/lo in MMA-fragment-major layouts ----------------
__global__ __launch_bounds__(256)
void decomp_kernel(const float* __restrict__ x) {
    __shared__ float sh[2*16*260];          // hi then lo, 16 rows x 260 (pad)
    int tid = threadIdx.x, rb = blockIdx.x;
    const float4* xs = reinterpret_cast<const float4*>(x + (size_t)rb*16*256);
    for (int p = 0; p < 4; p++) {
        int o = tid + p*256;                // 1024 float4
        int row = o >> 6, c4 = o & 63;
        float4 v = xs[o];
        float4 h, l;
        h.x = tf32r(v.x); h.y = tf32r(v.y); h.z = tf32r(v.z); h.w = tf32r(v.w);
        l.x = tf32r(v.x - h.x); l.y = tf32r(v.y - h.y);
        l.z = tf32r(v.z - h.z); l.w = tf32r(v.w - h.w);
        *reinterpret_cast<float4*>(&sh[row*260 + c4*4]) = h;
        *reinterpret_cast<float4*>(&sh[4160 + row*260 + c4*4]) = l;
    }
    __syncthreads();
    float* outA = g_xa + (size_t)rb * 8192;
    for (int p = 0; p < 32; p++) {
        int o = tid + p*256;                // 8192
        int k8 = o >> 7, le = o & 127, lane = le >> 2, reg = le & 3;
        int row = (lane >> 2) + 8*(reg & 1);
        int col = (lane & 3) + 4*(reg >> 1) + (k8 & 31)*8;
        outA[o] = sh[(k8 >> 5)*4160 + row*260 + col];
    }
    float* outB = g_xb + (size_t)rb * 8192;
    for (int p = 0; p < 32; p++) {
        int o = tid + p*256;
        int nbl = o >> 12, rem = o & 4095;
        int k8 = rem >> 6, le = rem & 63, lane = le >> 1, reg = le & 1;
        int row = nbl*8 + (lane >> 2);
        int col = (lane & 3) + 4*reg + (k8 & 31)*8;
        outB[o] = sh[(k8 >> 5)*4160 + row*260 + col];
    }
}

// ---------------- squared norms ----------------
__global__ void norms_kernel(const float* __restrict__ x) {
    int row  = blockIdx.x * 8 + (threadIdx.x >> 5);
    int lane = threadIdx.x & 31;
    const float4* xr = reinterpret_cast<const float4*>(x + (size_t)row * CC);
    float s = 0.f;
#pragma unroll
    for (int c = 0; c < 2; c++) {
        float4 v = xr[lane + 32*c];
        s += v.x*v.x + v.y*v.y + v.z*v.z + v.w*v.w;
    }
#pragma unroll
    for (int o = 16; o; o >>= 1) s += __shfl_xor_sync(0xffffffffu, s, o);
    if (lane == 0) g_sq[row] = s;
}

// ---------------- 3xTF32 mma.sync gram -> distance tiles ----------------
#define GRAM_SMEM_BYTES (67584 + 1024)
__global__ __launch_bounds__(256, 2)
void gram_mma_kernel() {
    int bx = blockIdx.x, by = blockIdx.y, bz = blockIdx.z;
    if (bx < by) return;

    extern __shared__ char smem[];
    uint32_t sb = smem_u32(smem);
    float* sc    = reinterpret_cast<float*>(smem);
    float* sqi_s = reinterpret_cast<float*>(smem + 67584);
    float* sqj_s = sqi_s + 128;

    int tid = threadIdx.x;
    int wid = tid >> 5, lane = tid & 31;
    int wi = wid >> 1, wj = wid & 1;
    int gid = lane >> 2, tig = lane & 3;

    if (tid < 128) sqi_s[tid] = g_sq[bz*NN + by*128 + tid];
    else           sqj_s[tid-128] = g_sq[bz*NN + bx*128 + (tid-128)];

    float acc[2][8][4];
#pragma unroll
    for (int m = 0; m < 2; m++)
#pragma unroll
        for (int n = 0; n < 8; n++)
#pragma unroll
            for (int r = 0; r < 4; r++) acc[m][n][r] = 0.f;

    const float4* xap = reinterpret_cast<const float4*>(g_xa);
    const float4* xbp = reinterpret_cast<const float4*>(g_xb);
    size_t rbbase = (size_t)bz*256 + (size_t)by*8;
    size_t nbbase = (size_t)bz*512 + (size_t)bx*16;

    const uint32_t aoff[2] = {0u, 16384u};
    const uint32_t boff[2] = {32768u, 49152u};

    auto stage = [&](int c) {
        int pass = c >> 3, kc = c & 7;
        int ak8 = ((pass == 2) ? 32 : 0) + kc*4;
        int bk8 = ((pass == 1) ? 32 : 0) + kc*4;
        int bsel = c & 1;
#pragma unroll
        for (int p = 0; p < 4; p++) {
            int o4 = tid + p*256;
            int rb = o4 >> 7, rem = o4 & 127;
            int k8l = rem >> 5, e4 = rem & 31;
            CP_ASYNC16(sb + aoff[bsel] + o4*16,
                       xap + ((rbbase + rb)*64 + ak8 + k8l)*32 + e4);
            int nb = o4 >> 6, rem2 = o4 & 63;
            int k8m = rem2 >> 4, e42 = rem2 & 15;
            CP_ASYNC16(sb + boff[bsel] + o4*16,
                       xbp + ((nbbase + nb)*64 + bk8 + k8m)*16 + e42);
        }
        CP_COMMIT();
    };

    stage(0);
    for (int c = 0; c < 24; c++) {
        if (c < 23) { stage(c + 1); CP_WAIT(1); }
        else        { CP_WAIT(0); }
        __syncthreads();
        int bsel = c & 1;
#pragma unroll
        for (int k8l = 0; k8l < 4; k8l++) {
            uint4 af[2]; uint2 bf[8];
#pragma unroll
            for (int m = 0; m < 2; m++)
                af[m] = *reinterpret_cast<const uint4*>(
                    smem + aoff[bsel] + (((wi*2 + m)*4 + k8l)*32 + lane)*16);
#pragma unroll
            for (int n = 0; n < 8; n++)
                bf[n] = *reinterpret_cast<const uint2*>(
                    smem + boff[bsel] + (((wj*8 + n)*4 + k8l)*32 + lane)*8);
#pragma unroll
            for (int m = 0; m < 2; m++)
#pragma unroll
                for (int n = 0; n < 8; n++)
                    MMA_TF32(acc[m][n], af[m], bf[n]);
        }
        __syncthreads();
    }

#pragma unroll
    for (int m = 0; m < 2; m++) {
#pragma unroll
        for (int n = 0; n < 8; n++) {
            int row = wi*32 + m*16 + gid;
            int col = wj*64 + n*8 + 2*tig;
            *reinterpret_cast<float2*>(&sc[row*132 + col]) =
                make_float2(acc[m][n][0], acc[m][n][1]);
            *reinterpret_cast<float2*>(&sc[(row + 8)*132 + col]) =
                make_float2(acc[m][n][2], acc[m][n][3]);
        }
    }
    __syncthreads();

    float* d2b = g_d2 + (size_t)bz * NN * NN;
    const float FINF = __int_as_float(0x7f800000);
#pragma unroll
    for (int p = 0; p < 16; p++) {
        int o = tid + p*256;
        int row = o >> 5, c4 = o & 31;
        float4 v = *reinterpret_cast<float4*>(&sc[row*132 + c4*4]);
        int gi = by*128 + row, gjb = bx*128 + c4*4;
        float si = sqi_s[row];
        float4 d;
        d.x = si + sqj_s[c4*4+0] - 2.f*v.x;
        d.y = si + sqj_s[c4*4+1] - 2.f*v.y;
        d.z = si + sqj_s[c4*4+2] - 2.f*v.z;
        d.w = si + sqj_s[c4*4+3] - 2.f*v.w;
        if (gi == gjb+0) d.x = FINF;
        if (gi == gjb+1) d.y = FINF;
        if (gi == gjb+2) d.z = FINF;
        if (gi == gjb+3) d.w = FINF;
        *reinterpret_cast<float4*>(d2b + (size_t)gi*NN + gjb) = d;
    }
    if (bx != by) {
#pragma unroll
        for (int p = 0; p < 16; p++) {
            int o = tid + p*256;
            int mr = o >> 5, q4 = o & 31;
            float sj = sqj_s[mr];
            float4 d;
            d.x = sqi_s[q4*4+0] + sj - 2.f*sc[(q4*4+0)*132 + mr];
            d.y = sqi_s[q4*4+1] + sj - 2.f*sc[(q4*4+1)*132 + mr];
            d.z = sqi_s[q4*4+2] + sj - 2.f*sc[(q4*4+2)*132 + mr];
            d.w = sqi_s[q4*4+3] + sj - 2.f*sc[(q4*4+3)*132 + mr];
            *reinterpret_cast<float4*>(d2b + (size_t)(bx*128 + mr)*NN + by*128 + q4*4) = d;
        }
    }
}

// ---------------- fused QKV GEMM ----------------
__global__ __launch_bounds__(256, 2)
void qkv_kernel(const float* __restrict__ x,
                const float* __restrict__ Wq, const float* __restrict__ bq,
                const float* __restrict__ Wk, const float* __restrict__ bk,
                const float* __restrict__ Wv, const float* __restrict__ bv) {
    __shared__ float As[32][128];
    __shared__ float Bs[32][128];

    const float* W; const float* bias; float* outp;
    if (blockIdx.z == 0)      { W = Wq; bias = bq; outp = g_q; }
    else if (blockIdx.z == 1) { W = Wk; bias = bk; outp = g_k; }
    else                      { W = Wv; bias = bv; outp = g_v; }

    int tid = threadIdx.x;
    int tx = tid & 15, ty = tid >> 4;
    int m0 = blockIdx.y * 128, n0 = blockIdx.x * 128;

    float acc[8][8];
#pragma unroll
    for (int i = 0; i < 8; i++)
#pragma unroll
        for (int j = 0; j < 8; j++) acc[i][j] = 0.f;

    for (int k0 = 0; k0 < CC; k0 += 32) {
#pragma unroll
        for (int p = 0; p < 4; p++) {
            int r = p*32 + (tid >> 3), c4 = tid & 7;
            float4 v = *reinterpret_cast<const float4*>(x + (size_t)(m0 + r)*CC + k0 + c4*4);
            As[c4*4+0][r] = v.x; As[c4*4+1][r] = v.y;
            As[c4*4+2][r] = v.z; As[c4*4+3][r] = v.w;
        }
#pragma unroll
        for (int p = 0; p < 4; p++) {
            int r = p*8 + (tid >> 5), c4 = tid & 31;
            *reinterpret_cast<float4*>(&Bs[r][c4*4]) =
                *reinterpret_cast<const float4*>(W + (size_t)(k0 + r)*HDIM + n0 + c4*4);
        }
        __syncthreads();
#pragma unroll
        for (int k = 0; k < 32; k++) {
            float a[8], b[8];
            *(float4*)(a)   = *(float4*)(&As[k][ty*8]);
            *(float4*)(a+4) = *(float4*)(&As[k][ty*8+4]);
            *(float4*)(b)   = *(float4*)(&Bs[k][tx*8]);
            *(float4*)(b+4) = *(float4*)(&Bs[k][tx*8+4]);
#pragma unroll
            for (int i = 0; i < 8; i++)
#pragma unroll
                for (int j = 0; j < 8; j++) acc[i][j] += a[i]*b[j];
        }
        __syncthreads();
    }
#pragma unroll
    for (int i = 0; i < 8; i++) {
        int m = m0 + ty*8 + i;
#pragma unroll
        for (int j4 = 0; j4 < 2; j4++) {
            int n = n0 + tx*8 + j4*4;
            float4 o;
            o.x = acc[i][j4*4+0] + bias[n+0];
            o.y = acc[i][j4*4+1] + bias[n+1];
            o.z = acc[i][j4*4+2] + bias[n+2];
            o.w = acc[i][j4*4+3] + bias[n+3];
            *reinterpret_cast<float4*>(outp + (size_t)m*HDIM + n) = o;
        }
    }
}

// ---------------- top-CAND approx candidates, exact fp32 re-rank -> top-16 ----------------
__global__ void topk_kernel(const float* __restrict__ x) {
    int row  = (blockIdx.x * blockDim.x + threadIdx.x) >> 5;   // 0..TOT-1
    int lane = threadIdx.x & 31;
    int bz = row >> 12, ri = row & (NN-1);
    const float4* rp = reinterpret_cast<const float4*>(g_d2 + (size_t)row * NN);
    const float FINF = __int_as_float(0x7f800000);

    float best[CAND]; int bidx[CAND];
#pragma unroll
    for (int t = 0; t < CAND; t++) { best[t] = FINF; bidx[t] = -1; }

    for (int it = 0; it < NN/128; it++) {
        float4 v = rp[it*32 + lane];
        int jb = (it*32 + lane) * 4;
        float dv[4] = {v.x, v.y, v.z, v.w};
#pragma unroll
        for (int c = 0; c < 4; c++) {
            float d = dv[c];
            if (d < best[0]) {
                best[0] = d; bidx[0] = jb + c;
#pragma unroll
                for (int t = 0; t < CAND-1; t++) {
                    if (best[t] < best[t+1]) {
                        float tv = best[t]; best[t] = best[t+1]; best[t+1] = tv;
                        int ti = bidx[t]; bidx[t] = bidx[t+1]; bidx[t+1] = ti;
                    }
                }
            }
        }
    }
    // extract warp-global approx top-CAND candidate indices
    int cand[CAND];
#pragma unroll
    for (int r = 0; r < CAND; r++) {
        unsigned long long key =
            ((unsigned long long)__float_as_uint(best[CAND-1]) << 32) | (unsigned)bidx[CAND-1];
        unsigned long long wk = key;
#pragma unroll
        for (int o = 16; o; o >>= 1) {
            unsigned long long other = __shfl_xor_sync(0xffffffffu, wk, o);
            if (other < wk) wk = other;
        }
        if (key == wk) {
#pragma unroll
            for (int t = CAND-1; t > 0; t--) { best[t] = best[t-1]; bidx[t] = bidx[t-1]; }
            best[0] = FINF; bidx[0] = -1;
        }
        cand[r] = (int)(wk & 0xffffffffu);
    }

    // exact fp32 re-rank of CAND candidates
    const float* xb = x + (size_t)bz * NN * CC;
    const float4* xi = reinterpret_cast<const float4*>(xb + (size_t)ri * CC);
    float4 xi0 = xi[lane*2], xi1 = xi[lane*2 + 1];
    float sqi = g_sq[row];
    float myd = FINF; int myidx = 0x7fffffff;
#pragma unroll
    for (int t = 0; t < CAND; t++) {
        int nb = cand[t];
        const float4* xj = reinterpret_cast<const float4*>(xb + (size_t)nb * CC);
        float4 a = xj[lane*2], b = xj[lane*2 + 1];
        float p = xi0.x*a.x + xi0.y*a.y + xi0.z*a.z + xi0.w*a.w
                + xi1.x*b.x + xi1.y*b.y + xi1.z*b.z + xi1.w*b.w;
#pragma unroll
        for (int o = 16; o; o >>= 1) p += __shfl_xor_sync(0xffffffffu, p, o);
        float d = sqi + g_sq[bz*NN + nb] - 2.f*p;
        if (lane == t) { myd = d; myidx = nb; }
    }
    // select exact top-16 (value-then-index order, matching top_k tie-break)
#pragma unroll
    for (int r = 0; r < KNN; r++) {
        unsigned long long key =
            ((unsigned long long)__float_as_uint(myd) << 32) | (unsigned)myidx;
        unsigned long long wk = key;
#pragma unroll
        for (int o = 16; o; o >>= 1) {
            unsigned long long other = __shfl_xor_sync(0xffffffffu, wk, o);
            if (other < wk) wk = other;
        }
        if (key == wk) myd = FINF;
        if (lane == 0) g_nbr[(size_t)row*KNN + r] = (int)(wk & 0xffffffffu);
    }
}

// ---------------- sparse attention: one warp per node, loop heads ----------------
__global__ void attn_kernel(float* __restrict__ out) {
    int node = (blockIdx.x * blockDim.x + threadIdx.x) >> 5;
    int lane = threadIdx.x & 31;
    int b = node >> 12;
    size_t base  = (size_t)node * HDIM;
    size_t bbase = (size_t)b * NN * HDIM;
    int nbr_l = g_nbr[(size_t)node*KNN + (lane & 15)];
    const float scale = 0.17677669529663687f;
    const float NINF = -__int_as_float(0x7f800000);

    for (int h = 0; h < NH; h++) {
        int off = h*DH + lane;
        float qd = g_q[base + off];
        float sc = 0.f;
#pragma unroll
        for (int kk = 0; kk < KNN; kk++) {
            int nb = __shfl_sync(0xffffffffu, nbr_l, kk);
            float p = qd * g_k[bbase + (size_t)nb*HDIM + off];
#pragma unroll
            for (int o = 16; o; o >>= 1) p += __shfl_xor_sync(0xffffffffu, p, o);
            if (lane == kk) sc = p * scale;
        }
        float m = (lane < 16) ? sc : NINF;
#pragma unroll
        for (int o = 16; o; o >>= 1) m = fmaxf(m, __shfl_xor_sync(0xffffffffu, m, o));
        float e = (lane < 16) ? expf(sc - m) : 0.f;
        float s = e;
#pragma unroll
        for (int o = 16; o; o >>= 1) s += __shfl_xor_sync(0xffffffffu, s, o);
        float alpha = e / s;
        float acc = 0.f;
#pragma unroll
        for (int kk = 0; kk < KNN; kk++) {
            float a = __shfl_sync(0xffffffffu, alpha, kk);
            int nb  = __shfl_sync(0xffffffffu, nbr_l, kk);
            acc += a * g_v[bbase + (size_t)nb*HDIM + off];
        }
        out[base + off] = acc;
    }
}

// ---------------- launch ----------------
extern "C" void kernel_launch(void* const* d_in, const int* in_sizes, int n_in,
                              void* d_out, int out_size) {
    const float* x  = (const float*)d_in[0];
    const float* Wq = (const float*)d_in[1];
    const float* bq = (const float*)d_in[2];
    const float* Wk = (const float*)d_in[3];
    const float* bk = (const float*)d_in[4];
    const float* Wv = (const float*)d_in[5];
    const float* bv = (const float*)d_in[6];
    float* out = (float*)d_out;

    cudaFuncSetAttribute(gram_mma_kernel,
                         cudaFuncAttributeMaxDynamicSharedMemorySize, GRAM_SMEM_BYTES);

    decomp_kernel<<<TOT/16, 256>>>(x);
    norms_kernel<<<TOT/8, 256>>>(x);
    gram_mma_kernel<<<dim3(NN/128, NN/128, NB), 256, GRAM_SMEM_BYTES>>>();
    topk_kernel<<<TOT/8, 256>>>(x);
    qkv_kernel<<<dim3(HDIM/128, TOT/128, 3), 256>>>(x, Wq, bq, Wk, bk, Wv, bv);
    attn_kernel<<<TOT/8, 256>>>(out);
}

// round 5
// speedup vs baseline: 1.4759x; 1.4608x over previous
#include <cuda_runtime.h>
#include <cstdint>
#include <math.h>

#define NB   4
#define NN   4096
#define CC   256
#define NH   8
#define DH   32
#define KNN  16
#define CAND 20
#define HDIM 256
#define TOT  (NB*NN)          // 16384 nodes total
#define TKCAP 1024            // per-warp candidate buffer entries

// ---------------- scratch (static device globals; no allocation) ----------------
__device__ float g_q [(size_t)TOT*HDIM];
__device__ float g_k [(size_t)TOT*HDIM];
__device__ float g_v [(size_t)TOT*HDIM];
__device__ float g_sq[TOT];
__device__ float g_d2[(size_t)NB*NN*NN];        // 268 MB distance matrix
__device__ float g_xa[(size_t)TOT*512];         // A-fragment layout hi|lo, 32 MB
__device__ float g_xb[(size_t)TOT*512];         // B-fragment layout hi|lo, 32 MB
__device__ int   g_nbr[(size_t)TOT*KNN];

// ================= helpers =================
__device__ __forceinline__ uint32_t smem_u32(const void* p) {
    uint32_t a;
    asm("{ .reg .u64 t; cvta.to.shared.u64 t, %1; cvt.u32.u64 %0, t; }" : "=r"(a) : "l"(p));
    return a;
}
#define CP_ASYNC16(saddr, gptr) \
    asm volatile("cp.async.cg.shared.global [%0], [%1], 16;" \
                 :: "r"((uint32_t)(saddr)), "l"(gptr) : "memory")
#define CP_COMMIT() asm volatile("cp.async.commit_group;" ::: "memory")
#define CP_WAIT(n)  asm volatile("cp.async.wait_group %0;" :: "n"(n) : "memory")

// mma.sync m16n8k8 tf32 (compute_80+, no 'a'-arch features)
#define MMA_TF32(c, a, b) \
    asm volatile("mma.sync.aligned.m16n8k8.row.col.f32.tf32.tf32.f32 " \
        "{%0,%1,%2,%3}, {%4,%5,%6,%7}, {%8,%9}, {%0,%1,%2,%3};" \
        : "+f"((c)[0]), "+f"((c)[1]), "+f"((c)[2]), "+f"((c)[3]) \
        : "r"((a).x), "r"((a).y), "r"((a).z), "r"((a).w), "r"((b).x), "r"((b).y))

__device__ __forceinline__ float tf32r(float v) {
    uint32_t u; asm("cvt.rna.tf32.f32 %0, %1;" : "=r"(u) : "f"(v));
    return __uint_as_float(u);
}

// ---------------- decomp: x -> tf32 hi/lo in MMA-fragment-major layouts ----------------
__global__ __launch_bounds__(256)
void decomp_kernel(const float* __restrict__ x) {
    __shared__ float sh[2*16*260];          // hi then lo, 16 rows x 260 (pad)
    int tid = threadIdx.x, rb = blockIdx.x;
    const float4* xs = reinterpret_cast<const float4*>(x + (size_t)rb*16*256);
    for (int p = 0; p < 4; p++) {
        int o = tid + p*256;                // 1024 float4
        int row = o >> 6, c4 = o & 63;
        float4 v = xs[o];
        float4 h, l;
        h.x = tf32r(v.x); h.y = tf32r(v.y); h.z = tf32r(v.z); h.w = tf32r(v.w);
        l.x = tf32r(v.x - h.x); l.y = tf32r(v.y - h.y);
        l.z = tf32r(v.z - h.z); l.w = tf32r(v.w - h.w);
        *reinterpret_cast<float4*>(&sh[row*260 + c4*4]) = h;
        *reinterpret_cast<float4*>(&sh[4160 + row*260 + c4*4]) = l;
    }
    __syncthreads();
    float* outA = g_xa + (size_t)rb * 8192;
    for (int p = 0; p < 32; p++) {
        int o = tid + p*256;                // 8192
        int k8 = o >> 7, le = o & 127, lane = le >> 2, reg = le & 3;
        int row = (lane >> 2) + 8*(reg & 1);
        int col = (lane & 3) + 4*(reg >> 1) + (k8 & 31)*8;
        outA[o] = sh[(k8 >> 5)*4160 + row*260 + col];
    }
    float* outB = g_xb + (size_t)rb * 8192;
    for (int p = 0; p < 32; p++) {
        int o = tid + p*256;
        int nbl = o >> 12, rem = o & 4095;
        int k8 = rem >> 6, le = rem & 63, lane = le >> 1, reg = le & 1;
        int row = nbl*8 + (lane >> 2);
        int col = (lane & 3) + 4*reg + (k8 & 31)*8;
        outB[o] = sh[(k8 >> 5)*4160 + row*260 + col];
    }
}

// ---------------- squared norms ----------------
__global__ void norms_kernel(const float* __restrict__ x) {
    int row  = blockIdx.x * 8 + (threadIdx.x >> 5);
    int lane = threadIdx.x & 31;
    const float4* xr = reinterpret_cast<const float4*>(x + (size_t)row * CC);
    float s = 0.f;
#pragma unroll
    for (int c = 0; c < 2; c++) {
        float4 v = xr[lane + 32*c];
        s += v.x*v.x + v.y*v.y + v.z*v.z + v.w*v.w;
    }
#pragma unroll
    for (int o = 16; o; o >>= 1) s += __shfl_xor_sync(0xffffffffu, s, o);
    if (lane == 0) g_sq[row] = s;
}

// ---------------- 3xTF32 mma.sync gram -> distance tiles ----------------
#define GRAM_SMEM_BYTES (67584 + 1024)
__global__ __launch_bounds__(256, 2)
void gram_mma_kernel() {
    int bx = blockIdx.x, by = blockIdx.y, bz = blockIdx.z;
    if (bx < by) return;

    extern __shared__ char smem[];
    uint32_t sb = smem_u32(smem);
    float* sc    = reinterpret_cast<float*>(smem);
    float* sqi_s = reinterpret_cast<float*>(smem + 67584);
    float* sqj_s = sqi_s + 128;

    int tid = threadIdx.x;
    int wid = tid >> 5, lane = tid & 31;
    int wi = wid >> 1, wj = wid & 1;
    int gid = lane >> 2, tig = lane & 3;

    if (tid < 128) sqi_s[tid] = g_sq[bz*NN + by*128 + tid];
    else           sqj_s[tid-128] = g_sq[bz*NN + bx*128 + (tid-128)];

    float acc[2][8][4];
#pragma unroll
    for (int m = 0; m < 2; m++)
#pragma unroll
        for (int n = 0; n < 8; n++)
#pragma unroll
            for (int r = 0; r < 4; r++) acc[m][n][r] = 0.f;

    const float4* xap = reinterpret_cast<const float4*>(g_xa);
    const float4* xbp = reinterpret_cast<const float4*>(g_xb);
    size_t rbbase = (size_t)bz*256 + (size_t)by*8;
    size_t nbbase = (size_t)bz*512 + (size_t)bx*16;

    const uint32_t aoff[2] = {0u, 16384u};
    const uint32_t boff[2] = {32768u, 49152u};

    auto stage = [&](int c) {
        int pass = c >> 3, kc = c & 7;
        int ak8 = ((pass == 2) ? 32 : 0) + kc*4;
        int bk8 = ((pass == 1) ? 32 : 0) + kc*4;
        int bsel = c & 1;
#pragma unroll
        for (int p = 0; p < 4; p++) {
            int o4 = tid + p*256;
            int rb = o4 >> 7, rem = o4 & 127;
            int k8l = rem >> 5, e4 = rem & 31;
            CP_ASYNC16(sb + aoff[bsel] + o4*16,
                       xap + ((rbbase + rb)*64 + ak8 + k8l)*32 + e4);
            int nb = o4 >> 6, rem2 = o4 & 63;
            int k8m = rem2 >> 4, e42 = rem2 & 15;
            CP_ASYNC16(sb + boff[bsel] + o4*16,
                       xbp + ((nbbase + nb)*64 + bk8 + k8m)*16 + e42);
        }
        CP_COMMIT();
    };

    stage(0);
    for (int c = 0; c < 24; c++) {
        if (c < 23) { stage(c + 1); CP_WAIT(1); }
        else        { CP_WAIT(0); }
        __syncthreads();
        int bsel = c & 1;
#pragma unroll
        for (int k8l = 0; k8l < 4; k8l++) {
            uint4 af[2]; uint2 bf[8];
#pragma unroll
            for (int m = 0; m < 2; m++)
                af[m] = *reinterpret_cast<const uint4*>(
                    smem + aoff[bsel] + (((wi*2 + m)*4 + k8l)*32 + lane)*16);
#pragma unroll
            for (int n = 0; n < 8; n++)
                bf[n] = *reinterpret_cast<const uint2*>(
                    smem + boff[bsel] + (((wj*8 + n)*4 + k8l)*32 + lane)*8);
#pragma unroll
            for (int m = 0; m < 2; m++)
#pragma unroll
                for (int n = 0; n < 8; n++)
                    MMA_TF32(acc[m][n], af[m], bf[n]);
        }
        __syncthreads();
    }

#pragma unroll
    for (int m = 0; m < 2; m++) {
#pragma unroll
        for (int n = 0; n < 8; n++) {
            int row = wi*32 + m*16 + gid;
            int col = wj*64 + n*8 + 2*tig;
            *reinterpret_cast<float2*>(&sc[row*132 + col]) =
                make_float2(acc[m][n][0], acc[m][n][1]);
            *reinterpret_cast<float2*>(&sc[(row + 8)*132 + col]) =
                make_float2(acc[m][n][2], acc[m][n][3]);
        }
    }
    __syncthreads();

    float* d2b = g_d2 + (size_t)bz * NN * NN;
    const float FINF = __int_as_float(0x7f800000);
#pragma unroll
    for (int p = 0; p < 16; p++) {
        int o = tid + p*256;
        int row = o >> 5, c4 = o & 31;
        float4 v = *reinterpret_cast<float4*>(&sc[row*132 + c4*4]);
        int gi = by*128 + row, gjb = bx*128 + c4*4;
        float si = sqi_s[row];
        float4 d;
        d.x = si + sqj_s[c4*4+0] - 2.f*v.x;
        d.y = si + sqj_s[c4*4+1] - 2.f*v.y;
        d.z = si + sqj_s[c4*4+2] - 2.f*v.z;
        d.w = si + sqj_s[c4*4+3] - 2.f*v.w;
        if (gi == gjb+0) d.x = FINF;
        if (gi == gjb+1) d.y = FINF;
        if (gi == gjb+2) d.z = FINF;
        if (gi == gjb+3) d.w = FINF;
        *reinterpret_cast<float4*>(d2b + (size_t)gi*NN + gjb) = d;
    }
    if (bx != by) {
#pragma unroll
        for (int p = 0; p < 16; p++) {
            int o = tid + p*256;
            int mr = o >> 5, q4 = o & 31;
            float sj = sqj_s[mr];
            float4 d;
            d.x = sqi_s[q4*4+0] + sj - 2.f*sc[(q4*4+0)*132 + mr];
            d.y = sqi_s[q4*4+1] + sj - 2.f*sc[(q4*4+1)*132 + mr];
            d.z = sqi_s[q4*4+2] + sj - 2.f*sc[(q4*4+2)*132 + mr];
            d.w = sqi_s[q4*4+3] + sj - 2.f*sc[(q4*4+3)*132 + mr];
            *reinterpret_cast<float4*>(d2b + (size_t)(bx*128 + mr)*NN + by*128 + q4*4) = d;
        }
    }
}

// ---------------- fused QKV GEMM ----------------
__global__ __launch_bounds__(256, 2)
void qkv_kernel(const float* __restrict__ x,
                const float* __restrict__ Wq, const float* __restrict__ bq,
                const float* __restrict__ Wk, const float* __restrict__ bk,
                const float* __restrict__ Wv, const float* __restrict__ bv) {
    __shared__ float As[32][128];
    __shared__ float Bs[32][128];

    const float* W; const float* bias; float* outp;
    if (blockIdx.z == 0)      { W = Wq; bias = bq; outp = g_q; }
    else if (blockIdx.z == 1) { W = Wk; bias = bk; outp = g_k; }
    else                      { W = Wv; bias = bv; outp = g_v; }

    int tid = threadIdx.x;
    int tx = tid & 15, ty = tid >> 4;
    int m0 = blockIdx.y * 128, n0 = blockIdx.x * 128;

    float acc[8][8];
#pragma unroll
    for (int i = 0; i < 8; i++)
#pragma unroll
        for (int j = 0; j < 8; j++) acc[i][j] = 0.f;

    for (int k0 = 0; k0 < CC; k0 += 32) {
#pragma unroll
        for (int p = 0; p < 4; p++) {
            int r = p*32 + (tid >> 3), c4 = tid & 7;
            float4 v = *reinterpret_cast<const float4*>(x + (size_t)(m0 + r)*CC + k0 + c4*4);
            As[c4*4+0][r] = v.x; As[c4*4+1][r] = v.y;
            As[c4*4+2][r] = v.z; As[c4*4+3][r] = v.w;
        }
#pragma unroll
        for (int p = 0; p < 4; p++) {
            int r = p*8 + (tid >> 5), c4 = tid & 31;
            *reinterpret_cast<float4*>(&Bs[r][c4*4]) =
                *reinterpret_cast<const float4*>(W + (size_t)(k0 + r)*HDIM + n0 + c4*4);
        }
        __syncthreads();
#pragma unroll
        for (int k = 0; k < 32; k++) {
            float a[8], b[8];
            *(float4*)(a)   = *(float4*)(&As[k][ty*8]);
            *(float4*)(a+4) = *(float4*)(&As[k][ty*8+4]);
            *(float4*)(b)   = *(float4*)(&Bs[k][tx*8]);
            *(float4*)(b+4) = *(float4*)(&Bs[k][tx*8+4]);
#pragma unroll
            for (int i = 0; i < 8; i++)
#pragma unroll
                for (int j = 0; j < 8; j++) acc[i][j] += a[i]*b[j];
        }
        __syncthreads();
    }
#pragma unroll
    for (int i = 0; i < 8; i++) {
        int m = m0 + ty*8 + i;
#pragma unroll
        for (int j4 = 0; j4 < 2; j4++) {
            int n = n0 + tx*8 + j4*4;
            float4 o;
            o.x = acc[i][j4*4+0] + bias[n+0];
            o.y = acc[i][j4*4+1] + bias[n+1];
            o.z = acc[i][j4*4+2] + bias[n+2];
            o.w = acc[i][j4*4+3] + bias[n+3];
            *reinterpret_cast<float4*>(outp + (size_t)m*HDIM + n) = o;
        }
    }
}

// ---------------- topk: threshold filter -> buffer -> exact fp32 rerank ----------------
#define TOPK_SMEM_BYTES (8 * TKCAP * 8)
__global__ __launch_bounds__(256)
void topk_kernel(const float* __restrict__ x) {
    extern __shared__ unsigned long long sbuf[];
    int tid  = threadIdx.x;
    int wip  = tid >> 5, lane = tid & 31;
    unsigned long long* buf = sbuf + (size_t)wip * TKCAP;
    int row = (blockIdx.x * blockDim.x + tid) >> 5;            // 0..TOT-1
    int bz = row >> 12, ri = row & (NN-1);
    const float4* rp = reinterpret_cast<const float4*>(g_d2 + (size_t)row * NN);
    const float FINF = __int_as_float(0x7f800000);

    // ---- pass 1: per-lane top-2 of float4-minima -> warp 20th-smallest = T ----
    float t1 = FINF, t2 = FINF;
    for (int it = 0; it < NN/128; it++) {
        float4 v = rp[it*32 + lane];
        float m = fminf(fminf(v.x, v.y), fminf(v.z, v.w));
        if (m < t2) {
            t2 = m;
            if (t2 < t1) { float tm = t1; t1 = t2; t2 = tm; }
        }
    }
    float T = FINF;
#pragma unroll
    for (int r = 0; r < CAND; r++) {
        float m = t1;
#pragma unroll
        for (int o = 16; o; o >>= 1) m = fminf(m, __shfl_xor_sync(0xffffffffu, m, o));
        if (t1 == m) { t1 = t2; t2 = FINF; }                  // kill winner(s)
        T = m;
    }

    // ---- pass 2: ballot-compact all elements <= T into per-warp buffer ----
    int cnt = 0;
    for (int it = 0; it < NN/128; it++) {
        float4 v = rp[it*32 + lane];
        int jb = (it*32 + lane) * 4;
        float dv[4] = {v.x, v.y, v.z, v.w};
#pragma unroll
        for (int c = 0; c < 4; c++) {
            bool p = (dv[c] <= T);
            unsigned msk = __ballot_sync(0xffffffffu, p);
            if (msk) {
                int off = cnt + __popc(msk & ((1u << lane) - 1u));
                if (p && off < TKCAP)
                    buf[off] = ((unsigned long long)__float_as_uint(dv[c]) << 32)
                             | (unsigned)(jb + c);
                cnt += __popc(msk);
            }
        }
    }
    if (cnt > TKCAP) cnt = TKCAP;
    __syncwarp();

    // ---- per-lane insertion over buffered items (few per lane) ----
    float best[CAND]; int bidx[CAND];
#pragma unroll
    for (int t = 0; t < CAND; t++) { best[t] = FINF; bidx[t] = -1; }
    for (int i = lane; i < cnt; i += 32) {
        unsigned long long k = buf[i];
        float d = __uint_as_float((unsigned)(k >> 32));
        int  j = (int)(k & 0xffffffffu);
        if (d < best[0]) {
            best[0] = d; bidx[0] = j;
#pragma unroll
            for (int t = 0; t < CAND-1; t++) {
                if (best[t] < best[t+1]) {
                    float tv = best[t]; best[t] = best[t+1]; best[t+1] = tv;
                    int ti = bidx[t]; bidx[t] = bidx[t+1]; bidx[t+1] = ti;
                }
            }
        }
    }

    // ---- extract warp-global approx top-CAND candidate indices ----
    int cand[CAND];
#pragma unroll
    for (int r = 0; r < CAND; r++) {
        unsigned long long key =
            ((unsigned long long)__float_as_uint(best[CAND-1]) << 32) | (unsigned)bidx[CAND-1];
        unsigned long long wk = key;
#pragma unroll
        for (int o = 16; o; o >>= 1) {
            unsigned long long other = __shfl_xor_sync(0xffffffffu, wk, o);
            if (other < wk) wk = other;
        }
        if (key == wk) {
#pragma unroll
            for (int t = CAND-1; t > 0; t--) { best[t] = best[t-1]; bidx[t] = bidx[t-1]; }
            best[0] = FINF; bidx[0] = -1;
        }
        cand[r] = (int)(wk & 0xffffffffu);
    }

    // ---- exact fp32 re-rank of CAND candidates ----
    const float* xb = x + (size_t)bz * NN * CC;
    const float4* xi = reinterpret_cast<const float4*>(xb + (size_t)ri * CC);
    float4 xi0 = xi[lane*2], xi1 = xi[lane*2 + 1];
    float sqi = g_sq[row];
    float myd = FINF; int myidx = 0x7fffffff;
#pragma unroll
    for (int t = 0; t < CAND; t++) {
        int nb = cand[t];
        const float4* xj = reinterpret_cast<const float4*>(xb + (size_t)nb * CC);
        float4 a = xj[lane*2], b = xj[lane*2 + 1];
        float p = xi0.x*a.x + xi0.y*a.y + xi0.z*a.z + xi0.w*a.w
                + xi1.x*b.x + xi1.y*b.y + xi1.z*b.z + xi1.w*b.w;
#pragma unroll
        for (int o = 16; o; o >>= 1) p += __shfl_xor_sync(0xffffffffu, p, o);
        float d = sqi + g_sq[bz*NN + nb] - 2.f*p;
        if (lane == t) { myd = d; myidx = nb; }
    }
    // ---- select exact top-16 (value-then-index, matching jax top_k) ----
#pragma unroll
    for (int r = 0; r < KNN; r++) {
        unsigned long long key =
            ((unsigned long long)__float_as_uint(myd) << 32) | (unsigned)myidx;
        unsigned long long wk = key;
#pragma unroll
        for (int o = 16; o; o >>= 1) {
            unsigned long long other = __shfl_xor_sync(0xffffffffu, wk, o);
            if (other < wk) wk = other;
        }
        if (key == wk) myd = FINF;
        if (lane == 0) g_nbr[(size_t)row*KNN + r] = (int)(wk & 0xffffffffu);
    }
}

// ---------------- sparse attention: one warp per node, loop heads ----------------
__global__ void attn_kernel(float* __restrict__ out) {
    int node = (blockIdx.x * blockDim.x + threadIdx.x) >> 5;
    int lane = threadIdx.x & 31;
    int b = node >> 12;
    size_t base  = (size_t)node * HDIM;
    size_t bbase = (size_t)b * NN * HDIM;
    int nbr_l = g_nbr[(size_t)node*KNN + (lane & 15)];
    const float scale = 0.17677669529663687f;
    const float NINF = -__int_as_float(0x7f800000);

    for (int h = 0; h < NH; h++) {
        int off = h*DH + lane;
        float qd = g_q[base + off];
        float sc = 0.f;
#pragma unroll
        for (int kk = 0; kk < KNN; kk++) {
            int nb = __shfl_sync(0xffffffffu, nbr_l, kk);
            float p = qd * g_k[bbase + (size_t)nb*HDIM + off];
#pragma unroll
            for (int o = 16; o; o >>= 1) p += __shfl_xor_sync(0xffffffffu, p, o);
            if (lane == kk) sc = p * scale;
        }
        float m = (lane < 16) ? sc : NINF;
#pragma unroll
        for (int o = 16; o; o >>= 1) m = fmaxf(m, __shfl_xor_sync(0xffffffffu, m, o));
        float e = (lane < 16) ? expf(sc - m) : 0.f;
        float s = e;
#pragma unroll
        for (int o = 16; o; o >>= 1) s += __shfl_xor_sync(0xffffffffu, s, o);
        float alpha = e / s;
        float acc = 0.f;
#pragma unroll
        for (int kk = 0; kk < KNN; kk++) {
            float a = __shfl_sync(0xffffffffu, alpha, kk);
            int nb  = __shfl_sync(0xffffffffu, nbr_l, kk);
            acc += a * g_v[bbase + (size_t)nb*HDIM + off];
        }
        out[base + off] = acc;
    }
}

// ---------------- launch ----------------
extern "C" void kernel_launch(void* const* d_in, const int* in_sizes, int n_in,
                              void* d_out, int out_size) {
    const float* x  = (const float*)d_in[0];
    const float* Wq = (const float*)d_in[1];
    const float* bq = (const float*)d_in[2];
    const float* Wk = (const float*)d_in[3];
    const float* bk = (const float*)d_in[4];
    const float* Wv = (const float*)d_in[5];
    const float* bv = (const float*)d_in[6];
    float* out = (float*)d_out;

    cudaFuncSetAttribute(gram_mma_kernel,
                         cudaFuncAttributeMaxDynamicSharedMemorySize, GRAM_SMEM_BYTES);
    cudaFuncSetAttribute(topk_kernel,
                         cudaFuncAttributeMaxDynamicSharedMemorySize, TOPK_SMEM_BYTES);

    decomp_kernel<<<TOT/16, 256>>>(x);
    norms_kernel<<<TOT/8, 256>>>(x);
    gram_mma_kernel<<<dim3(NN/128, NN/128, NB), 256, GRAM_SMEM_BYTES>>>();
    topk_kernel<<<TOT/8, 256, TOPK_SMEM_BYTES>>>(x);
    qkv_kernel<<<dim3(HDIM/128, TOT/128, 3), 256>>>(x, Wq, bq, Wk, bk, Wv, bv);
    attn_kernel<<<TOT/8, 256>>>(out);
}

// round 7
// speedup vs baseline: 1.8008x; 1.2201x over previous
#include <cuda_runtime.h>
#include <cstdint>
#include <math.h>

#define NB   4
#define NN   4096
#define CC   256
#define NH   8
#define DH   32
#define KNN  16
#define CAND 24
#define HDIM 256
#define TOT  (NB*NN)          // 16384 nodes total
#define TKCAP 1024            // per-warp candidate buffer entries

// ---------------- scratch (static device globals; no allocation) ----------------
__device__ float g_q [(size_t)TOT*HDIM];
__device__ float g_k [(size_t)TOT*HDIM];
__device__ float g_v [(size_t)TOT*HDIM];
__device__ float g_sq[TOT];
__device__ float g_d2[(size_t)NB*NN*NN];        // 268 MB distance matrix
__device__ float g_xa[(size_t)TOT*256];         // A-fragment layout (tf32 hi), 16 MB
__device__ float g_xb[(size_t)TOT*256];         // B-fragment layout (tf32 hi), 16 MB
__device__ int   g_nbr[(size_t)TOT*KNN];

// ================= helpers =================
__device__ __forceinline__ uint32_t smem_u32(const void* p) {
    uint32_t a;
    asm("{ .reg .u64 t; cvta.to.shared.u64 t, %1; cvt.u32.u64 %0, t; }" : "=r"(a) : "l"(p));
    return a;
}
#define CP_ASYNC16(saddr, gptr) \
    asm volatile("cp.async.cg.shared.global [%0], [%1], 16;" \
                 :: "r"((uint32_t)(saddr)), "l"(gptr) : "memory")
#define CP_COMMIT() asm volatile("cp.async.commit_group;" ::: "memory")
#define CP_WAIT(n)  asm volatile("cp.async.wait_group %0;" :: "n"(n) : "memory")

// mma.sync m16n8k8 tf32 (compute_80+, no 'a'-arch features)
#define MMA_TF32(c, a, b) \
    asm volatile("mma.sync.aligned.m16n8k8.row.col.f32.tf32.tf32.f32 " \
        "{%0,%1,%2,%3}, {%4,%5,%6,%7}, {%8,%9}, {%0,%1,%2,%3};" \
        : "+f"((c)[0]), "+f"((c)[1]), "+f"((c)[2]), "+f"((c)[3]) \
        : "r"((a).x), "r"((a).y), "r"((a).z), "r"((a).w), "r"((b).x), "r"((b).y))

__device__ __forceinline__ float tf32r(float v) {
    uint32_t u; asm("cvt.rna.tf32.f32 %0, %1;" : "=r"(u) : "f"(v));
    return __uint_as_float(u);
}

// ---------------- decomp: x -> tf32(hi) in MMA-fragment-major layouts ----------------
// One CTA = one 16-row block of x.
// g_xa blocks (16 rows, 4096 floats): [rb16][k8(0..31)][lane(0..31)][reg(0..3)]
//   element(lane,reg): row=(lane>>2)+8*(reg&1), col=(lane&3)+4*(reg>>1)+k8*8
// g_xb blocks (8 rows, 2048 floats): [nb8][k8(0..31)][lane][reg(0..1)]
//   element: row=lane>>2, col=(lane&3)+4*reg+k8*8
__global__ __launch_bounds__(256)
void decomp_kernel(const float* __restrict__ x) {
    __shared__ float sh[16*260];            // 16 rows x 260 (pad)
    int tid = threadIdx.x, rb = blockIdx.x;
    const float4* xs = reinterpret_cast<const float4*>(x + (size_t)rb*16*256);
    for (int p = 0; p < 4; p++) {
        int o = tid + p*256;                // 1024 float4
        int row = o >> 6, c4 = o & 63;
        float4 v = xs[o];
        float4 h;
        h.x = tf32r(v.x); h.y = tf32r(v.y); h.z = tf32r(v.z); h.w = tf32r(v.w);
        *reinterpret_cast<float4*>(&sh[row*260 + c4*4]) = h;
    }
    __syncthreads();
    float* outA = g_xa + (size_t)rb * 4096;
    for (int p = 0; p < 16; p++) {
        int o = tid + p*256;                // 4096
        int k8 = o >> 7, le = o & 127, lane = le >> 2, reg = le & 3;
        int row = (lane >> 2) + 8*(reg & 1);
        int col = (lane & 3) + 4*(reg >> 1) + k8*8;
        outA[o] = sh[row*260 + col];
    }
    float* outB = g_xb + (size_t)rb * 4096;
    for (int p = 0; p < 16; p++) {
        int o = tid + p*256;
        int nbl = o >> 11, rem = o & 2047;
        int k8 = rem >> 6, le = rem & 63, lane = le >> 1, reg = le & 1;
        int row = nbl*8 + (lane >> 2);
        int col = (lane & 3) + 4*reg + k8*8;
        outB[o] = sh[row*260 + col];
    }
}

// ---------------- squared norms ----------------
__global__ void norms_kernel(const float* __restrict__ x) {
    int row  = blockIdx.x * 8 + (threadIdx.x >> 5);
    int lane = threadIdx.x & 31;
    const float4* xr = reinterpret_cast<const float4*>(x + (size_t)row * CC);
    float s = 0.f;
#pragma unroll
    for (int c = 0; c < 2; c++) {
        float4 v = xr[lane + 32*c];
        s += v.x*v.x + v.y*v.y + v.z*v.z + v.w*v.w;
    }
#pragma unroll
    for (int o = 16; o; o >>= 1) s += __shfl_xor_sync(0xffffffffu, s, o);
    if (lane == 0) g_sq[row] = s;
}

// ---------------- single-pass tf32 mma.sync gram -> distance tiles ----------------
// K = 256 (hi only) in 8 chunks of 32, cp.async double buffered.
// CTA tile 128x128, 8 warps as 4(i) x 2(j), warp tile 32x64.
#define GRAM_SMEM_BYTES (67584 + 1024)
__global__ __launch_bounds__(256, 2)
void gram_mma_kernel() {
    int bx = blockIdx.x, by = blockIdx.y, bz = blockIdx.z;
    if (bx < by) return;

    extern __shared__ char smem[];
    uint32_t sb = smem_u32(smem);
    float* sc    = reinterpret_cast<float*>(smem);
    float* sqi_s = reinterpret_cast<float*>(smem + 67584);
    float* sqj_s = sqi_s + 128;

    int tid = threadIdx.x;
    int wid = tid >> 5, lane = tid & 31;
    int wi = wid >> 1, wj = wid & 1;
    int gid = lane >> 2, tig = lane & 3;

    if (tid < 128) sqi_s[tid] = g_sq[bz*NN + by*128 + tid];
    else           sqj_s[tid-128] = g_sq[bz*NN + bx*128 + (tid-128)];

    float acc[2][8][4];
#pragma unroll
    for (int m = 0; m < 2; m++)
#pragma unroll
        for (int n = 0; n < 8; n++)
#pragma unroll
            for (int r = 0; r < 4; r++) acc[m][n][r] = 0.f;

    const float4* xap = reinterpret_cast<const float4*>(g_xa);
    const float4* xbp = reinterpret_cast<const float4*>(g_xb);
    size_t rbbase = (size_t)bz*256 + (size_t)by*8;    // 16-row block base (A): 256/batch
    size_t nbbase = (size_t)bz*512 + (size_t)bx*16;   // 8-row block base (B): 512/batch

    const uint32_t aoff[2] = {0u, 16384u};
    const uint32_t boff[2] = {32768u, 49152u};

    auto stage = [&](int c) {
        int k8b = c*4;
        int bsel = c & 1;
#pragma unroll
        for (int p = 0; p < 4; p++) {
            int o4 = tid + p*256;
            int rb = o4 >> 7, rem = o4 & 127;
            int k8l = rem >> 5, e4 = rem & 31;
            CP_ASYNC16(sb + aoff[bsel] + o4*16,
                       xap + ((rbbase + rb)*32 + k8b + k8l)*32 + e4);
            int nb = o4 >> 6, rem2 = o4 & 63;
            int k8m = rem2 >> 4, e42 = rem2 & 15;
            CP_ASYNC16(sb + boff[bsel] + o4*16,
                       xbp + ((nbbase + nb)*32 + k8b + k8m)*16 + e42);
        }
        CP_COMMIT();
    };

    stage(0);
    for (int c = 0; c < 8; c++) {
        if (c < 7) { stage(c + 1); CP_WAIT(1); }
        else       { CP_WAIT(0); }
        __syncthreads();
        int bsel = c & 1;
#pragma unroll
        for (int k8l = 0; k8l < 4; k8l++) {
            uint4 af[2]; uint2 bf[8];
#pragma unroll
            for (int m = 0; m < 2; m++)
                af[m] = *reinterpret_cast<const uint4*>(
                    smem + aoff[bsel] + (((wi*2 + m)*4 + k8l)*32 + lane)*16);
#pragma unroll
            for (int n = 0; n < 8; n++)
                bf[n] = *reinterpret_cast<const uint2*>(
                    smem + boff[bsel] + (((wj*8 + n)*4 + k8l)*32 + lane)*8);
#pragma unroll
            for (int m = 0; m < 2; m++)
#pragma unroll
                for (int n = 0; n < 8; n++)
                    MMA_TF32(acc[m][n], af[m], bf[n]);
        }
        __syncthreads();
    }

#pragma unroll
    for (int m = 0; m < 2; m++) {
#pragma unroll
        for (int n = 0; n < 8; n++) {
            int row = wi*32 + m*16 + gid;
            int col = wj*64 + n*8 + 2*tig;
            *reinterpret_cast<float2*>(&sc[row*132 + col]) =
                make_float2(acc[m][n][0], acc[m][n][1]);
            *reinterpret_cast<float2*>(&sc[(row + 8)*132 + col]) =
                make_float2(acc[m][n][2], acc[m][n][3]);
        }
    }
    __syncthreads();

    float* d2b = g_d2 + (size_t)bz * NN * NN;
    const float FINF = __int_as_float(0x7f800000);
#pragma unroll
    for (int p = 0; p < 16; p++) {
        int o = tid + p*256;
        int row = o >> 5, c4 = o & 31;
        float4 v = *reinterpret_cast<float4*>(&sc[row*132 + c4*4]);
        int gi = by*128 + row, gjb = bx*128 + c4*4;
        float si = sqi_s[row];
        float4 d;
        d.x = si + sqj_s[c4*4+0] - 2.f*v.x;
        d.y = si + sqj_s[c4*4+1] - 2.f*v.y;
        d.z = si + sqj_s[c4*4+2] - 2.f*v.z;
        d.w = si + sqj_s[c4*4+3] - 2.f*v.w;
        if (gi == gjb+0) d.x = FINF;
        if (gi == gjb+1) d.y = FINF;
        if (gi == gjb+2) d.z = FINF;
        if (gi == gjb+3) d.w = FINF;
        *reinterpret_cast<float4*>(d2b + (size_t)gi*NN + gjb) = d;
    }
    if (bx != by) {
#pragma unroll
        for (int p = 0; p < 16; p++) {
            int o = tid + p*256;
            int mr = o >> 5, q4 = o & 31;
            float sj = sqj_s[mr];
            float4 d;
            d.x = sqi_s[q4*4+0] + sj - 2.f*sc[(q4*4+0)*132 + mr];
            d.y = sqi_s[q4*4+1] + sj - 2.f*sc[(q4*4+1)*132 + mr];
            d.z = sqi_s[q4*4+2] + sj - 2.f*sc[(q4*4+2)*132 + mr];
            d.w = sqi_s[q4*4+3] + sj - 2.f*sc[(q4*4+3)*132 + mr];
            *reinterpret_cast<float4*>(d2b + (size_t)(bx*128 + mr)*NN + by*128 + q4*4) = d;
        }
    }
}

// ---------------- fused QKV GEMM ----------------
__global__ __launch_bounds__(256, 2)
void qkv_kernel(const float* __restrict__ x,
                const float* __restrict__ Wq, const float* __restrict__ bq,
                const float* __restrict__ Wk, const float* __restrict__ bk,
                const float* __restrict__ Wv, const float* __restrict__ bv) {
    __shared__ float As[32][128];
    __shared__ float Bs[32][128];

    const float* W; const float* bias; float* outp;
    if (blockIdx.z == 0)      { W = Wq; bias = bq; outp = g_q; }
    else if (blockIdx.z == 1) { W = Wk; bias = bk; outp = g_k; }
    else                      { W = Wv; bias = bv; outp = g_v; }

    int tid = threadIdx.x;
    int tx = tid & 15, ty = tid >> 4;
    int m0 = blockIdx.y * 128, n0 = blockIdx.x * 128;

    float acc[8][8];
#pragma unroll
    for (int i = 0; i < 8; i++)
#pragma unroll
        for (int j = 0; j < 8; j++) acc[i][j] = 0.f;

    for (int k0 = 0; k0 < CC; k0 += 32) {
#pragma unroll
        for (int p = 0; p < 4; p++) {
            int r = p*32 + (tid >> 3), c4 = tid & 7;
            float4 v = *reinterpret_cast<const float4*>(x + (size_t)(m0 + r)*CC + k0 + c4*4);
            As[c4*4+0][r] = v.x; As[c4*4+1][r] = v.y;
            As[c4*4+2][r] = v.z; As[c4*4+3][r] = v.w;
        }
#pragma unroll
        for (int p = 0; p < 4; p++) {
            int r = p*8 + (tid >> 5), c4 = tid & 31;
            *reinterpret_cast<float4*>(&Bs[r][c4*4]) =
                *reinterpret_cast<const float4*>(W + (size_t)(k0 + r)*HDIM + n0 + c4*4);
        }
        __syncthreads();
#pragma unroll
        for (int k = 0; k < 32; k++) {
            float a[8], b[8];
            *(float4*)(a)   = *(float4*)(&As[k][ty*8]);
            *(float4*)(a+4) = *(float4*)(&As[k][ty*8+4]);
            *(float4*)(b)   = *(float4*)(&Bs[k][tx*8]);
            *(float4*)(b+4) = *(float4*)(&Bs[k][tx*8+4]);
#pragma unroll
            for (int i = 0; i < 8; i++)
#pragma unroll
                for (int j = 0; j < 8; j++) acc[i][j] += a[i]*b[j];
        }
        __syncthreads();
    }
#pragma unroll
    for (int i = 0; i < 8; i++) {
        int m = m0 + ty*8 + i;
#pragma unroll
        for (int j4 = 0; j4 < 2; j4++) {
            int n = n0 + tx*8 + j4*4;
            float4 o;
            o.x = acc[i][j4*4+0] + bias[n+0];
            o.y = acc[i][j4*4+1] + bias[n+1];
            o.z = acc[i][j4*4+2] + bias[n+2];
            o.w = acc[i][j4*4+3] + bias[n+3];
            *reinterpret_cast<float4*>(outp + (size_t)m*HDIM + n) = o;
        }
    }
}

// ---------------- topk: threshold filter -> buffer -> exact fp32 rerank ----------------
#define TOPK_SMEM_BYTES (8 * TKCAP * 8)
__global__ __launch_bounds__(256)
void topk_kernel(const float* __restrict__ x) {
    extern __shared__ unsigned long long sbuf[];
    int tid  = threadIdx.x;
    int wip  = tid >> 5, lane = tid & 31;
    unsigned long long* buf = sbuf + (size_t)wip * TKCAP;
    int row = (blockIdx.x * blockDim.x + tid) >> 5;            // 0..TOT-1
    int bz = row >> 12, ri = row & (NN-1);
    const float4* rp = reinterpret_cast<const float4*>(g_d2 + (size_t)row * NN);
    const float FINF = __int_as_float(0x7f800000);

    // ---- pass 1: per-lane top-2 of float4-minima -> warp CAND-th smallest = T ----
    float t1 = FINF, t2 = FINF;
    for (int it = 0; it < NN/128; it++) {
        float4 v = rp[it*32 + lane];
        float m = fminf(fminf(v.x, v.y), fminf(v.z, v.w));
        if (m < t2) {
            t2 = m;
            if (t2 < t1) { float tm = t1; t1 = t2; t2 = tm; }
        }
    }
    float T = FINF;
#pragma unroll
    for (int r = 0; r < CAND; r++) {
        float m = t1;
#pragma unroll
        for (int o = 16; o; o >>= 1) m = fminf(m, __shfl_xor_sync(0xffffffffu, m, o));
        if (t1 == m) { t1 = t2; t2 = FINF; }                  // kill winner(s)
        T = m;
    }

    // ---- pass 2: ballot-compact all elements <= T into per-warp buffer ----
    int cnt = 0;
    for (int it = 0; it < NN/128; it++) {
        float4 v = rp[it*32 + lane];
        int jb = (it*32 + lane) * 4;
        float dv[4] = {v.x, v.y, v.z, v.w};
#pragma unroll
        for (int c = 0; c < 4; c++) {
            bool p = (dv[c] <= T);
            unsigned msk = __ballot_sync(0xffffffffu, p);
            if (msk) {
                int off = cnt + __popc(msk & ((1u << lane) - 1u));
                if (p && off < TKCAP)
                    buf[off] = ((unsigned long long)__float_as_uint(dv[c]) << 32)
                             | (unsigned)(jb + c);
                cnt += __popc(msk);
            }
        }
    }
    if (cnt > TKCAP) cnt = TKCAP;
    __syncwarp();

    // ---- per-lane insertion over buffered items (few per lane) ----
    float best[CAND]; int bidx[CAND];
#pragma unroll
    for (int t = 0; t < CAND; t++) { best[t] = FINF; bidx[t] = -1; }
    for (int i = lane; i < cnt; i += 32) {
        unsigned long long k = buf[i];
        float d = __uint_as_float((unsigned)(k >> 32));
        int  j = (int)(k & 0xffffffffu);
        if (d < best[0]) {
            best[0] = d; bidx[0] = j;
#pragma unroll
            for (int t = 0; t < CAND-1; t++) {
                if (best[t] < best[t+1]) {
                    float tv = best[t]; best[t] = best[t+1]; best[t+1] = tv;
                    int ti = bidx[t]; bidx[t] = bidx[t+1]; bidx[t+1] = ti;
                }
            }
        }
    }

    // ---- extract warp-global approx top-CAND candidate indices ----
    int cand[CAND];
#pragma unroll
    for (int r = 0; r < CAND; r++) {
        unsigned long long key =
            ((unsigned long long)__float_as_uint(best[CAND-1]) << 32) | (unsigned)bidx[CAND-1];
        unsigned long long wk = key;
#pragma unroll
        for (int o = 16; o; o >>= 1) {
            unsigned long long other = __shfl_xor_sync(0xffffffffu, wk, o);
            if (other < wk) wk = other;
        }
        if (key == wk) {
#pragma unroll
            for (int t = CAND-1; t > 0; t--) { best[t] = best[t-1]; bidx[t] = bidx[t-1]; }
            best[0] = FINF; bidx[0] = -1;
        }
        cand[r] = (int)(wk & 0xffffffffu);
    }

    // ---- exact fp32 re-rank of CAND candidates ----
    const float* xb = x + (size_t)bz * NN * CC;
    const float4* xi = reinterpret_cast<const float4*>(xb + (size_t)ri * CC);
    float4 xi0 = xi[lane*2], xi1 = xi[lane*2 + 1];
    float sqi = g_sq[row];
    float myd = FINF; int myidx = 0x7fffffff;
#pragma unroll
    for (int t = 0; t < CAND; t++) {
        int nb = cand[t];
        const float4* xj = reinterpret_cast<const float4*>(xb + (size_t)nb * CC);
        float4 a = xj[lane*2], b = xj[lane*2 + 1];
        float p = xi0.x*a.x + xi0.y*a.y + xi0.z*a.z + xi0.w*a.w
                + xi1.x*b.x + xi1.y*b.y + xi1.z*b.z + xi1.w*b.w;
#pragma unroll
        for (int o = 16; o; o >>= 1) p += __shfl_xor_sync(0xffffffffu, p, o);
        float d = sqi + g_sq[bz*NN + nb] - 2.f*p;
        if (lane == t) { myd = d; myidx = nb; }
    }
    // ---- select exact top-16 (value-then-index, matching jax top_k) ----
#pragma unroll
    for (int r = 0; r < KNN; r++) {
        unsigned long long key =
            ((unsigned long long)__float_as_uint(myd) << 32) | (unsigned)myidx;
        unsigned long long wk = key;
#pragma unroll
        for (int o = 16; o; o >>= 1) {
            unsigned long long other = __shfl_xor_sync(0xffffffffu, wk, o);
            if (other < wk) wk = other;
        }
        if (key == wk) myd = FINF;
        if (lane == 0) g_nbr[(size_t)row*KNN + r] = (int)(wk & 0xffffffffu);
    }
}

// ---------------- sparse attention: one warp per node, loop heads ----------------
__global__ void attn_kernel(float* __restrict__ out) {
    int node = (blockIdx.x * blockDim.x + threadIdx.x) >> 5;
    int lane = threadIdx.x & 31;
    int b = node >> 12;
    size_t base  = (size_t)node * HDIM;
    size_t bbase = (size_t)b * NN * HDIM;
    int nbr_l = g_nbr[(size_t)node*KNN + (lane & 15)];
    const float scale = 0.17677669529663687f;
    const float NINF = -__int_as_float(0x7f800000);

    for (int h = 0; h < NH; h++) {
        int off = h*DH + lane;
        float qd = g_q[base + off];
        float sc = 0.f;
#pragma unroll
        for (int kk = 0; kk < KNN; kk++) {
            int nb = __shfl_sync(0xffffffffu, nbr_l, kk);
            float p = qd * g_k[bbase + (size_t)nb*HDIM + off];
#pragma unroll
            for (int o = 16; o; o >>= 1) p += __shfl_xor_sync(0xffffffffu, p, o);
            if (lane == kk) sc = p * scale;
        }
        float m = (lane < 16) ? sc : NINF;
#pragma unroll
        for (int o = 16; o; o >>= 1) m = fmaxf(m, __shfl_xor_sync(0xffffffffu, m, o));
        float e = (lane < 16) ? expf(sc - m) : 0.f;
        float s = e;
#pragma unroll
        for (int o = 16; o; o >>= 1) s += __shfl_xor_sync(0xffffffffu, s, o);
        float alpha = e / s;
        float acc = 0.f;
#pragma unroll
        for (int kk = 0; kk < KNN; kk++) {
            float a = __shfl_sync(0xffffffffu, alpha, kk);
            int nb  = __shfl_sync(0xffffffffu, nbr_l, kk);
            acc += a * g_v[bbase + (size_t)nb*HDIM + off];
        }
        out[base + off] = acc;
    }
}

// ---------------- launch ----------------
extern "C" void kernel_launch(void* const* d_in, const int* in_sizes, int n_in,
                              void* d_out, int out_size) {
    const float* x  = (const float*)d_in[0];
    const float* Wq = (const float*)d_in[1];
    const float* bq = (const float*)d_in[2];
    const float* Wk = (const float*)d_in[3];
    const float* bk = (const float*)d_in[4];
    const float* Wv = (const float*)d_in[5];
    const float* bv = (const float*)d_in[6];
    float* out = (float*)d_out;

    cudaFuncSetAttribute(gram_mma_kernel,
                         cudaFuncAttributeMaxDynamicSharedMemorySize, GRAM_SMEM_BYTES);
    cudaFuncSetAttribute(topk_kernel,
                         cudaFuncAttributeMaxDynamicSharedMemorySize, TOPK_SMEM_BYTES);

    decomp_kernel<<<TOT/16, 256>>>(x);
    norms_kernel<<<TOT/8, 256>>>(x);
    gram_mma_kernel<<<dim3(NN/128, NN/128, NB), 256, GRAM_SMEM_BYTES>>>();
    topk_kernel<<<TOT/8, 256, TOPK_SMEM_BYTES>>>(x);
    qkv_kernel<<<dim3(HDIM/128, TOT/128, 3), 256>>>(x, Wq, bq, Wk, bk, Wv, bv);
    attn_kernel<<<TOT/8, 256>>>(out);
}

// round 9
// speedup vs baseline: 1.9717x; 1.0949x over previous
#include <cuda_runtime.h>
#include <cstdint>
#include <math.h>

#define NB   4
#define NN   4096
#define CC   256
#define NH   8
#define DH   32
#define KNN  16
#define CAND 24
#define HDIM 256
#define TOT  (NB*NN)          // 16384 nodes total
#define TKCAP 1024            // per-warp candidate buffer entries

// ---------------- scratch (static device globals; no allocation) ----------------
__device__ float  g_q [(size_t)TOT*HDIM];
__device__ float  g_k [(size_t)TOT*HDIM];
__device__ float  g_v [(size_t)TOT*HDIM];
__device__ float  g_sq[TOT];
__device__ float  g_d2[(size_t)NB*NN*NN];       // 268 MB distance matrix (fp32)
__device__ float  g_xa [(size_t)TOT*256];       // A-fragment layout, tf32 hi
__device__ float  g_xal[(size_t)TOT*256];       // A-fragment layout, tf32 lo
__device__ float  g_xb [(size_t)TOT*256];       // B-fragment layout, tf32 hi
__device__ float  g_wbh[3*65536];               // W  B-fragment hi (q,k,v)
__device__ float  g_wbl[3*65536];               // W  B-fragment lo
__device__ int    g_nbr[(size_t)TOT*KNN];

// ================= helpers =================
__device__ __forceinline__ uint32_t smem_u32(const void* p) {
    uint32_t a;
    asm("{ .reg .u64 t; cvta.to.shared.u64 t, %1; cvt.u32.u64 %0, t; }" : "=r"(a) : "l"(p));
    return a;
}
#define CP_ASYNC16(saddr, gptr) \
    asm volatile("cp.async.cg.shared.global [%0], [%1], 16;" \
                 :: "r"((uint32_t)(saddr)), "l"(gptr) : "memory")
#define CP_COMMIT() asm volatile("cp.async.commit_group;" ::: "memory")
#define CP_WAIT(n)  asm volatile("cp.async.wait_group %0;" :: "n"(n) : "memory")

// mma.sync m16n8k8 tf32 (compute_80+, no 'a'-arch features)
#define MMA_TF32(c, a, b) \
    asm volatile("mma.sync.aligned.m16n8k8.row.col.f32.tf32.tf32.f32 " \
        "{%0,%1,%2,%3}, {%4,%5,%6,%7}, {%8,%9}, {%0,%1,%2,%3};" \
        : "+f"((c)[0]), "+f"((c)[1]), "+f"((c)[2]), "+f"((c)[3]) \
        : "r"((a).x), "r"((a).y), "r"((a).z), "r"((a).w), "r"((b).x), "r"((b).y))

__device__ __forceinline__ float tf32r(float v) {
    uint32_t u; asm("cvt.rna.tf32.f32 %0, %1;" : "=r"(u) : "f"(v));
    return __uint_as_float(u);
}

// ---------------- decomp: x -> tf32 hi/lo in MMA-fragment-major layouts ----------------
// A blocks (16 rows, 4096 floats): [rb16][k8(0..31)][lane][reg(0..3)]
//   element(lane,reg): row=(lane>>2)+8*(reg&1), col=(lane&3)+4*(reg>>1)+k8*8
// B blocks (8 rows, 2048 floats): [nb8][k8(0..31)][lane][reg(0..1)]
//   element: row=lane>>2, col=(lane&3)+4*reg+k8*8
__global__ __launch_bounds__(256)
void decomp_kernel(const float* __restrict__ x) {
    __shared__ float sh[16*260];
    __shared__ float sl[16*260];
    int tid = threadIdx.x, rb = blockIdx.x;
    const float4* xs = reinterpret_cast<const float4*>(x + (size_t)rb*16*256);
    for (int p = 0; p < 4; p++) {
        int o = tid + p*256;                // 1024 float4
        int row = o >> 6, c4 = o & 63;
        float4 v = xs[o];
        float4 h, l;
        h.x = tf32r(v.x); h.y = tf32r(v.y); h.z = tf32r(v.z); h.w = tf32r(v.w);
        l.x = tf32r(v.x - h.x); l.y = tf32r(v.y - h.y);
        l.z = tf32r(v.z - h.z); l.w = tf32r(v.w - h.w);
        *reinterpret_cast<float4*>(&sh[row*260 + c4*4]) = h;
        *reinterpret_cast<float4*>(&sl[row*260 + c4*4]) = l;
    }
    __syncthreads();
    float* outA  = g_xa  + (size_t)rb * 4096;
    float* outAl = g_xal + (size_t)rb * 4096;
    for (int p = 0; p < 16; p++) {
        int o = tid + p*256;                // 4096
        int k8 = o >> 7, le = o & 127, lane = le >> 2, reg = le & 3;
        int row = (lane >> 2) + 8*(reg & 1);
        int col = (lane & 3) + 4*(reg >> 1) + k8*8;
        int si = row*260 + col;
        outA[o]  = sh[si];
        outAl[o] = sl[si];
    }
    float* outB = g_xb + (size_t)rb * 4096;
    for (int p = 0; p < 16; p++) {
        int o = tid + p*256;
        int nbl = o >> 11, rem = o & 2047;
        int k8 = rem >> 6, le = rem & 63, lane = le >> 1, reg = le & 1;
        int row = nbl*8 + (lane >> 2);
        int col = (lane & 3) + 4*reg + k8*8;
        outB[o] = sh[row*260 + col];
    }
}

// ---------------- W -> B-fragment hi/lo (3 x 256x256) ----------------
__global__ void wdecomp_kernel(const float* __restrict__ Wq,
                               const float* __restrict__ Wk,
                               const float* __restrict__ Wv) {
    int z = blockIdx.y;
    const float* W = (z == 0) ? Wq : ((z == 1) ? Wk : Wv);
    int idx = blockIdx.x * 256 + threadIdx.x;   // 0..65535
    int nb = idx >> 11, rem = idx & 2047;
    int k8 = rem >> 6, le = rem & 63, lane = le >> 1, reg = le & 1;
    int n = nb*8 + (lane >> 2);
    int k = (lane & 3) + 4*reg + k8*8;
    float w = W[k*HDIM + n];
    float h = tf32r(w);
    g_wbh[z*65536 + idx] = h;
    g_wbl[z*65536 + idx] = tf32r(w - h);
}

// ---------------- squared norms ----------------
__global__ void norms_kernel(const float* __restrict__ x) {
    int row  = blockIdx.x * 8 + (threadIdx.x >> 5);
    int lane = threadIdx.x & 31;
    const float4* xr = reinterpret_cast<const float4*>(x + (size_t)row * CC);
    float s = 0.f;
#pragma unroll
    for (int c = 0; c < 2; c++) {
        float4 v = xr[lane + 32*c];
        s += v.x*v.x + v.y*v.y + v.z*v.z + v.w*v.w;
    }
#pragma unroll
    for (int o = 16; o; o >>= 1) s += __shfl_xor_sync(0xffffffffu, s, o);
    if (lane == 0) g_sq[row] = s;
}

// ---------------- single-pass tf32 mma.sync gram -> fp32 distance tiles ----------------
#define GRAM_SMEM_BYTES (67584 + 1024)
__global__ __launch_bounds__(256, 2)
void gram_mma_kernel() {
    int bx = blockIdx.x, by = blockIdx.y, bz = blockIdx.z;
    if (bx < by) return;

    extern __shared__ char smem[];
    uint32_t sb = smem_u32(smem);
    float* sc    = reinterpret_cast<float*>(smem);
    float* sqi_s = reinterpret_cast<float*>(smem + 67584);
    float* sqj_s = sqi_s + 128;

    int tid = threadIdx.x;
    int wid = tid >> 5, lane = tid & 31;
    int wi = wid >> 1, wj = wid & 1;
    int gid = lane >> 2, tig = lane & 3;

    if (tid < 128) sqi_s[tid] = g_sq[bz*NN + by*128 + tid];
    else           sqj_s[tid-128] = g_sq[bz*NN + bx*128 + (tid-128)];

    float acc[2][8][4];
#pragma unroll
    for (int m = 0; m < 2; m++)
#pragma unroll
        for (int n = 0; n < 8; n++)
#pragma unroll
            for (int r = 0; r < 4; r++) acc[m][n][r] = 0.f;

    const float4* xap = reinterpret_cast<const float4*>(g_xa);
    const float4* xbp = reinterpret_cast<const float4*>(g_xb);
    size_t rbbase = (size_t)bz*256 + (size_t)by*8;
    size_t nbbase = (size_t)bz*512 + (size_t)bx*16;

    const uint32_t aoff[2] = {0u, 16384u};
    const uint32_t boff[2] = {32768u, 49152u};

    auto stage = [&](int c) {
        int k8b = c*4;
        int bsel = c & 1;
#pragma unroll
        for (int p = 0; p < 4; p++) {
            int o4 = tid + p*256;
            int rb = o4 >> 7, rem = o4 & 127;
            int k8l = rem >> 5, e4 = rem & 31;
            CP_ASYNC16(sb + aoff[bsel] + o4*16,
                       xap + ((rbbase + rb)*32 + k8b + k8l)*32 + e4);
            int nb = o4 >> 6, rem2 = o4 & 63;
            int k8m = rem2 >> 4, e42 = rem2 & 15;
            CP_ASYNC16(sb + boff[bsel] + o4*16,
                       xbp + ((nbbase + nb)*32 + k8b + k8m)*16 + e42);
        }
        CP_COMMIT();
    };

    stage(0);
    for (int c = 0; c < 8; c++) {
        if (c < 7) { stage(c + 1); CP_WAIT(1); }
        else       { CP_WAIT(0); }
        __syncthreads();
        int bsel = c & 1;
#pragma unroll
        for (int k8l = 0; k8l < 4; k8l++) {
            uint4 af[2]; uint2 bf[8];
#pragma unroll
            for (int m = 0; m < 2; m++)
                af[m] = *reinterpret_cast<const uint4*>(
                    smem + aoff[bsel] + (((wi*2 + m)*4 + k8l)*32 + lane)*16);
#pragma unroll
            for (int n = 0; n < 8; n++)
                bf[n] = *reinterpret_cast<const uint2*>(
                    smem + boff[bsel] + (((wj*8 + n)*4 + k8l)*32 + lane)*8);
#pragma unroll
            for (int m = 0; m < 2; m++)
#pragma unroll
                for (int n = 0; n < 8; n++)
                    MMA_TF32(acc[m][n], af[m], bf[n]);
        }
        __syncthreads();
    }

#pragma unroll
    for (int m = 0; m < 2; m++) {
#pragma unroll
        for (int n = 0; n < 8; n++) {
            int row = wi*32 + m*16 + gid;
            int col = wj*64 + n*8 + 2*tig;
            *reinterpret_cast<float2*>(&sc[row*132 + col]) =
                make_float2(acc[m][n][0], acc[m][n][1]);
            *reinterpret_cast<float2*>(&sc[(row + 8)*132 + col]) =
                make_float2(acc[m][n][2], acc[m][n][3]);
        }
    }
    __syncthreads();

    float* d2b = g_d2 + (size_t)bz * NN * NN;
    const float FINF = __int_as_float(0x7f800000);
#pragma unroll
    for (int p = 0; p < 16; p++) {
        int o = tid + p*256;
        int row = o >> 5, c4 = o & 31;
        float4 v = *reinterpret_cast<float4*>(&sc[row*132 + c4*4]);
        int gi = by*128 + row, gjb = bx*128 + c4*4;
        float si = sqi_s[row];
        float4 d;
        d.x = si + sqj_s[c4*4+0] - 2.f*v.x;
        d.y = si + sqj_s[c4*4+1] - 2.f*v.y;
        d.z = si + sqj_s[c4*4+2] - 2.f*v.z;
        d.w = si + sqj_s[c4*4+3] - 2.f*v.w;
        if (gi == gjb+0) d.x = FINF;
        if (gi == gjb+1) d.y = FINF;
        if (gi == gjb+2) d.z = FINF;
        if (gi == gjb+3) d.w = FINF;
        *reinterpret_cast<float4*>(d2b + (size_t)gi*NN + gjb) = d;
    }
    if (bx != by) {
#pragma unroll
        for (int p = 0; p < 16; p++) {
            int o = tid + p*256;
            int mr = o >> 5, q4 = o & 31;
            float sj = sqj_s[mr];
            float4 d;
            d.x = sqi_s[q4*4+0] + sj - 2.f*sc[(q4*4+0)*132 + mr];
            d.y = sqi_s[q4*4+1] + sj - 2.f*sc[(q4*4+1)*132 + mr];
            d.z = sqi_s[q4*4+2] + sj - 2.f*sc[(q4*4+2)*132 + mr];
            d.w = sqi_s[q4*4+3] + sj - 2.f*sc[(q4*4+3)*132 + mr];
            *reinterpret_cast<float4*>(d2b + (size_t)(bx*128 + mr)*NN + by*128 + q4*4) = d;
        }
    }
}

// ---------------- qkv via 3xTF32 mma.sync: out = x @ W + b ----------------
// grid (2 ncol-tiles, 128 row-tiles, 3 weights). 24 chunks: pass0 hi.hi,
// pass1 hi.lo(W), pass2 lo(x).hi.
#define QKV_SMEM_BYTES 65536
__global__ __launch_bounds__(256, 2)
void qkv_mma_kernel(const float* __restrict__ bq,
                    const float* __restrict__ bk,
                    const float* __restrict__ bv) {
    int bx = blockIdx.x, by = blockIdx.y, z = blockIdx.z;
    extern __shared__ char smem[];
    uint32_t sb = smem_u32(smem);

    int tid = threadIdx.x;
    int wid = tid >> 5, lane = tid & 31;
    int wi = wid >> 1, wj = wid & 1;
    int gid = lane >> 2, tig = lane & 3;

    const float* bias = (z == 0) ? bq : ((z == 1) ? bk : bv);
    float* outp = (z == 0) ? g_q : ((z == 1) ? g_k : g_v);

    float acc[2][8][4];
#pragma unroll
    for (int m = 0; m < 2; m++)
#pragma unroll
        for (int n = 0; n < 8; n++)
#pragma unroll
            for (int r = 0; r < 4; r++) acc[m][n][r] = 0.f;

    const float4* xah = reinterpret_cast<const float4*>(g_xa);
    const float4* xal = reinterpret_cast<const float4*>(g_xal);
    const float4* wbh = reinterpret_cast<const float4*>(g_wbh) + (size_t)z*16384;
    const float4* wbl = reinterpret_cast<const float4*>(g_wbl) + (size_t)z*16384;
    size_t rbbase = (size_t)by*8;
    size_t nbbase = (size_t)bx*16;

    const uint32_t aoff[2] = {0u, 16384u};
    const uint32_t boff[2] = {32768u, 49152u};

    auto stage = [&](int c) {
        int pass = c >> 3, kc = c & 7;
        int k8b = kc*4;
        int bsel = c & 1;
        const float4* asrc = (pass == 2) ? xal : xah;
        const float4* bsrc = (pass == 1) ? wbl : wbh;
#pragma unroll
        for (int p = 0; p < 4; p++) {
            int o4 = tid + p*256;
            int rb = o4 >> 7, rem = o4 & 127;
            int k8l = rem >> 5, e4 = rem & 31;
            CP_ASYNC16(sb + aoff[bsel] + o4*16,
                       asrc + ((rbbase + rb)*32 + k8b + k8l)*32 + e4);
            int nb = o4 >> 6, rem2 = o4 & 63;
            int k8m = rem2 >> 4, e42 = rem2 & 15;
            CP_ASYNC16(sb + boff[bsel] + o4*16,
                       bsrc + ((nbbase + nb)*32 + k8b + k8m)*16 + e42);
        }
        CP_COMMIT();
    };

    stage(0);
    for (int c = 0; c < 24; c++) {
        if (c < 23) { stage(c + 1); CP_WAIT(1); }
        else        { CP_WAIT(0); }
        __syncthreads();
        int bsel = c & 1;
#pragma unroll
        for (int k8l = 0; k8l < 4; k8l++) {
            uint4 af[2]; uint2 bf[8];
#pragma unroll
            for (int m = 0; m < 2; m++)
                af[m] = *reinterpret_cast<const uint4*>(
                    smem + aoff[bsel] + (((wi*2 + m)*4 + k8l)*32 + lane)*16);
#pragma unroll
            for (int n = 0; n < 8; n++)
                bf[n] = *reinterpret_cast<const uint2*>(
                    smem + boff[bsel] + (((wj*8 + n)*4 + k8l)*32 + lane)*8);
#pragma unroll
            for (int m = 0; m < 2; m++)
#pragma unroll
                for (int n = 0; n < 8; n++)
                    MMA_TF32(acc[m][n], af[m], bf[n]);
        }
        __syncthreads();
    }

    // epilogue: bias + direct store
#pragma unroll
    for (int m = 0; m < 2; m++) {
#pragma unroll
        for (int n = 0; n < 8; n++) {
            int row = by*128 + wi*32 + m*16 + gid;
            int col = bx*128 + wj*64 + n*8 + 2*tig;
            float2 bb = *reinterpret_cast<const float2*>(bias + col);
            *reinterpret_cast<float2*>(outp + (size_t)row*HDIM + col) =
                make_float2(acc[m][n][0] + bb.x, acc[m][n][1] + bb.y);
            *reinterpret_cast<float2*>(outp + (size_t)(row+8)*HDIM + col) =
                make_float2(acc[m][n][2] + bb.x, acc[m][n][3] + bb.y);
        }
    }
}

// ---------------- topk: fp32 threshold filter -> buffer -> exact fp32 rerank ----------------
#define TOPK_SMEM_BYTES (8 * TKCAP * 8)
__global__ __launch_bounds__(256)
void topk_kernel(const float* __restrict__ x) {
    extern __shared__ unsigned long long sbuf[];
    int tid  = threadIdx.x;
    int wip  = tid >> 5, lane = tid & 31;
    unsigned long long* buf = sbuf + (size_t)wip * TKCAP;
    int row = (blockIdx.x * blockDim.x + tid) >> 5;            // 0..TOT-1
    int bz = row >> 12, ri = row & (NN-1);
    const float4* rp = reinterpret_cast<const float4*>(g_d2 + (size_t)row * NN);
    const float FINF = __int_as_float(0x7f800000);

    // ---- pass 1: per-lane top-2 of float4-minima -> warp CAND-th smallest = T ----
    float t1 = FINF, t2 = FINF;
    for (int it = 0; it < NN/128; it++) {
        float4 v = rp[it*32 + lane];
        float m = fminf(fminf(v.x, v.y), fminf(v.z, v.w));
        if (m < t2) {
            t2 = m;
            if (t2 < t1) { float tm = t1; t1 = t2; t2 = tm; }
        }
    }
    float T = FINF;
#pragma unroll
    for (int r = 0; r < CAND; r++) {
        float m = t1;
#pragma unroll
        for (int o = 16; o; o >>= 1) m = fminf(m, __shfl_xor_sync(0xffffffffu, m, o));
        if (t1 == m) { t1 = t2; t2 = FINF; }                  // kill winner(s)
        T = m;
    }

    // ---- pass 2: ballot-compact all elements <= T into per-warp buffer ----
    int cnt = 0;
    for (int it = 0; it < NN/128; it++) {
        float4 v = rp[it*32 + lane];
        int jb = (it*32 + lane) * 4;
        float dv[4] = {v.x, v.y, v.z, v.w};
#pragma unroll
        for (int c = 0; c < 4; c++) {
            bool p = (dv[c] <= T);
            unsigned msk = __ballot_sync(0xffffffffu, p);
            if (msk) {
                int off = cnt + __popc(msk & ((1u << lane) - 1u));
                if (p && off < TKCAP)
                    buf[off] = ((unsigned long long)__float_as_uint(dv[c]) << 32)
                             | (unsigned)(jb + c);
                cnt += __popc(msk);
            }
        }
    }
    if (cnt > TKCAP) cnt = TKCAP;
    __syncwarp();

    // ---- per-lane insertion over buffered items (few per lane) ----
    float best[CAND]; int bidx[CAND];
#pragma unroll
    for (int t = 0; t < CAND; t++) { best[t] = FINF; bidx[t] = -1; }
    for (int i = lane; i < cnt; i += 32) {
        unsigned long long k = buf[i];
        float d = __uint_as_float((unsigned)(k >> 32));
        int  j = (int)(k & 0xffffffffu);
        if (d < best[0]) {
            best[0] = d; bidx[0] = j;
#pragma unroll
            for (int t = 0; t < CAND-1; t++) {
                if (best[t] < best[t+1]) {
                    float tv = best[t]; best[t] = best[t+1]; best[t+1] = tv;
                    int ti = bidx[t]; bidx[t] = bidx[t+1]; bidx[t+1] = ti;
                }
            }
        }
    }

    // ---- extract warp-global approx top-CAND candidate indices ----
    int cand[CAND];
#pragma unroll
    for (int r = 0; r < CAND; r++) {
        unsigned long long key =
            ((unsigned long long)__float_as_uint(best[CAND-1]) << 32) | (unsigned)bidx[CAND-1];
        unsigned long long wk = key;
#pragma unroll
        for (int o = 16; o; o >>= 1) {
            unsigned long long other = __shfl_xor_sync(0xffffffffu, wk, o);
            if (other < wk) wk = other;
        }
        if (key == wk) {
#pragma unroll
            for (int t = CAND-1; t > 0; t--) { best[t] = best[t-1]; bidx[t] = bidx[t-1]; }
            best[0] = FINF; bidx[0] = -1;
        }
        cand[r] = (int)(wk & 0xffffffffu);
    }

    // ---- exact fp32 re-rank of CAND candidates ----
    const float* xb = x + (size_t)bz * NN * CC;
    const float4* xi = reinterpret_cast<const float4*>(xb + (size_t)ri * CC);
    float4 xi0 = xi[lane*2], xi1 = xi[lane*2 + 1];
    float sqi = g_sq[row];
    float myd = FINF; int myidx = 0x7fffffff;
#pragma unroll
    for (int t = 0; t < CAND; t++) {
        int nb = cand[t];
        const float4* xj = reinterpret_cast<const float4*>(xb + (size_t)nb * CC);
        float4 a = xj[lane*2], b = xj[lane*2 + 1];
        float p = xi0.x*a.x + xi0.y*a.y + xi0.z*a.z + xi0.w*a.w
                + xi1.x*b.x + xi1.y*b.y + xi1.z*b.z + xi1.w*b.w;
#pragma unroll
        for (int o = 16; o; o >>= 1) p += __shfl_xor_sync(0xffffffffu, p, o);
        float d = sqi + g_sq[bz*NN + nb] - 2.f*p;
        if (lane == t) { myd = d; myidx = nb; }
    }
    // ---- select exact top-16 (value-then-index, matching jax top_k) ----
#pragma unroll
    for (int r = 0; r < KNN; r++) {
        unsigned long long key =
            ((unsigned long long)__float_as_uint(myd) << 32) | (unsigned)myidx;
        unsigned long long wk = key;
#pragma unroll
        for (int o = 16; o; o >>= 1) {
            unsigned long long other = __shfl_xor_sync(0xffffffffu, wk, o);
            if (other < wk) wk = other;
        }
        if (key == wk) myd = FINF;
        if (lane == 0) g_nbr[(size_t)row*KNN + r] = (int)(wk & 0xffffffffu);
    }
}

// ---------------- sparse attention: one warp per node, loop heads ----------------
__global__ void attn_kernel(float* __restrict__ out) {
    int node = (blockIdx.x * blockDim.x + threadIdx.x) >> 5;
    int lane = threadIdx.x & 31;
    int b = node >> 12;
    size_t base  = (size_t)node * HDIM;
    size_t bbase = (size_t)b * NN * HDIM;
    int nbr_l = g_nbr[(size_t)node*KNN + (lane & 15)];
    const float scale = 0.17677669529663687f;
    const float NINF = -__int_as_float(0x7f800000);

    for (int h = 0; h < NH; h++) {
        int off = h*DH + lane;
        float qd = g_q[base + off];
        float sc = 0.f;
#pragma unroll
        for (int kk = 0; kk < KNN; kk++) {
            int nb = __shfl_sync(0xffffffffu, nbr_l, kk);
            float p = qd * g_k[bbase + (size_t)nb*HDIM + off];
#pragma unroll
            for (int o = 16; o; o >>= 1) p += __shfl_xor_sync(0xffffffffu, p, o);
            if (lane == kk) sc = p * scale;
        }
        float m = (lane < 16) ? sc : NINF;
#pragma unroll
        for (int o = 16; o; o >>= 1) m = fmaxf(m, __shfl_xor_sync(0xffffffffu, m, o));
        float e = (lane < 16) ? expf(sc - m) : 0.f;
        float s = e;
#pragma unroll
        for (int o = 16; o; o >>= 1) s += __shfl_xor_sync(0xffffffffu, s, o);
        float alpha = e / s;
        float acc = 0.f;
#pragma unroll
        for (int kk = 0; kk < KNN; kk++) {
            float a = __shfl_sync(0xffffffffu, alpha, kk);
            int nb  = __shfl_sync(0xffffffffu, nbr_l, kk);
            acc += a * g_v[bbase + (size_t)nb*HDIM + off];
        }
        out[base + off] = acc;
    }
}

// ---------------- launch ----------------
extern "C" void kernel_launch(void* const* d_in, const int* in_sizes, int n_in,
                              void* d_out, int out_size) {
    const float* x  = (const float*)d_in[0];
    const float* Wq = (const float*)d_in[1];
    const float* bq = (const float*)d_in[2];
    const float* Wk = (const float*)d_in[3];
    const float* bk = (const float*)d_in[4];
    const float* Wv = (const float*)d_in[5];
    const float* bv = (const float*)d_in[6];
    float* out = (float*)d_out;

    cudaFuncSetAttribute(gram_mma_kernel,
                         cudaFuncAttributeMaxDynamicSharedMemorySize, GRAM_SMEM_BYTES);
    cudaFuncSetAttribute(qkv_mma_kernel,
                         cudaFuncAttributeMaxDynamicSharedMemorySize, QKV_SMEM_BYTES);
    cudaFuncSetAttribute(topk_kernel,
                         cudaFuncAttributeMaxDynamicSharedMemorySize, TOPK_SMEM_BYTES);

    decomp_kernel<<<TOT/16, 256>>>(x);
    wdecomp_kernel<<<dim3(256, 3), 256>>>(Wq, Wk, Wv);
    norms_kernel<<<TOT/8, 256>>>(x);
    gram_mma_kernel<<<dim3(NN/128, NN/128, NB), 256, GRAM_SMEM_BYTES>>>();
    topk_kernel<<<TOT/8, 256, TOPK_SMEM_BYTES>>>(x);
    qkv_mma_kernel<<<dim3(2, TOT/128, 3), 256, QKV_SMEM_BYTES>>>(bq, bk, bv);
    attn_kernel<<<TOT/8, 256>>>(out);
}

// round 10
// speedup vs baseline: 2.0438x; 1.0366x over previous
#include <cuda_runtime.h>
#include <cstdint>
#include <math.h>

#define NB   4
#define NN   4096
#define CC   256
#define NH   8
#define DH   32
#define KNN  16
#define CAND 24
#define HDIM 256
#define TOT  (NB*NN)          // 16384 nodes total
#define TKCAP 512             // per-warp candidate buffer entries

// ---------------- scratch (static device globals; no allocation) ----------------
__device__ float  g_q [(size_t)TOT*HDIM];
__device__ float  g_k [(size_t)TOT*HDIM];
__device__ float  g_v [(size_t)TOT*HDIM];
__device__ float  g_sq[TOT];
__device__ float  g_d2[(size_t)NB*NN*NN];       // 268 MB distance matrix (fp32)
__device__ float  g_xa [(size_t)TOT*256];       // A-fragment layout, tf32 hi
__device__ float  g_xal[(size_t)TOT*256];       // A-fragment layout, tf32 lo
__device__ float  g_xb [(size_t)TOT*256];       // B-fragment layout, tf32 hi
__device__ float  g_wbh[3*65536];               // W  B-fragment hi (q,k,v)
__device__ float  g_wbl[3*65536];               // W  B-fragment lo
__device__ int    g_nbr[(size_t)TOT*KNN];

// ================= helpers =================
__device__ __forceinline__ uint32_t smem_u32(const void* p) {
    uint32_t a;
    asm("{ .reg .u64 t; cvta.to.shared.u64 t, %1; cvt.u32.u64 %0, t; }" : "=r"(a) : "l"(p));
    return a;
}
#define CP_ASYNC16(saddr, gptr) \
    asm volatile("cp.async.cg.shared.global [%0], [%1], 16;" \
                 :: "r"((uint32_t)(saddr)), "l"(gptr) : "memory")
#define CP_COMMIT() asm volatile("cp.async.commit_group;" ::: "memory")
#define CP_WAIT(n)  asm volatile("cp.async.wait_group %0;" :: "n"(n) : "memory")

// mma.sync m16n8k8 tf32 (compute_80+, no 'a'-arch features)
#define MMA_TF32(c, a, b) \
    asm volatile("mma.sync.aligned.m16n8k8.row.col.f32.tf32.tf32.f32 " \
        "{%0,%1,%2,%3}, {%4,%5,%6,%7}, {%8,%9}, {%0,%1,%2,%3};" \
        : "+f"((c)[0]), "+f"((c)[1]), "+f"((c)[2]), "+f"((c)[3]) \
        : "r"((a).x), "r"((a).y), "r"((a).z), "r"((a).w), "r"((b).x), "r"((b).y))

__device__ __forceinline__ float tf32r(float v) {
    uint32_t u; asm("cvt.rna.tf32.f32 %0, %1;" : "=r"(u) : "f"(v));
    return __uint_as_float(u);
}

// ---------------- decomp: x -> tf32 hi/lo in MMA-fragment-major layouts ----------------
__global__ __launch_bounds__(256)
void decomp_kernel(const float* __restrict__ x) {
    __shared__ float sh[16*260];
    __shared__ float sl[16*260];
    int tid = threadIdx.x, rb = blockIdx.x;
    const float4* xs = reinterpret_cast<const float4*>(x + (size_t)rb*16*256);
    for (int p = 0; p < 4; p++) {
        int o = tid + p*256;                // 1024 float4
        int row = o >> 6, c4 = o & 63;
        float4 v = xs[o];
        float4 h, l;
        h.x = tf32r(v.x); h.y = tf32r(v.y); h.z = tf32r(v.z); h.w = tf32r(v.w);
        l.x = tf32r(v.x - h.x); l.y = tf32r(v.y - h.y);
        l.z = tf32r(v.z - h.z); l.w = tf32r(v.w - h.w);
        *reinterpret_cast<float4*>(&sh[row*260 + c4*4]) = h;
        *reinterpret_cast<float4*>(&sl[row*260 + c4*4]) = l;
    }
    __syncthreads();
    float* outA  = g_xa  + (size_t)rb * 4096;
    float* outAl = g_xal + (size_t)rb * 4096;
    for (int p = 0; p < 16; p++) {
        int o = tid + p*256;                // 4096
        int k8 = o >> 7, le = o & 127, lane = le >> 2, reg = le & 3;
        int row = (lane >> 2) + 8*(reg & 1);
        int col = (lane & 3) + 4*(reg >> 1) + k8*8;
        int si = row*260 + col;
        outA[o]  = sh[si];
        outAl[o] = sl[si];
    }
    float* outB = g_xb + (size_t)rb * 4096;
    for (int p = 0; p < 16; p++) {
        int o = tid + p*256;
        int nbl = o >> 11, rem = o & 2047;
        int k8 = rem >> 6, le = rem & 63, lane = le >> 1, reg = le & 1;
        int row = nbl*8 + (lane >> 2);
        int col = (lane & 3) + 4*reg + k8*8;
        outB[o] = sh[row*260 + col];
    }
}

// ---------------- W -> B-fragment hi/lo (3 x 256x256) ----------------
__global__ void wdecomp_kernel(const float* __restrict__ Wq,
                               const float* __restrict__ Wk,
                               const float* __restrict__ Wv) {
    int z = blockIdx.y;
    const float* W = (z == 0) ? Wq : ((z == 1) ? Wk : Wv);
    int idx = blockIdx.x * 256 + threadIdx.x;   // 0..65535
    int nb = idx >> 11, rem = idx & 2047;
    int k8 = rem >> 6, le = rem & 63, lane = le >> 1, reg = le & 1;
    int n = nb*8 + (lane >> 2);
    int k = (lane & 3) + 4*reg + k8*8;
    float w = W[k*HDIM + n];
    float h = tf32r(w);
    g_wbh[z*65536 + idx] = h;
    g_wbl[z*65536 + idx] = tf32r(w - h);
}

// ---------------- squared norms ----------------
__global__ void norms_kernel(const float* __restrict__ x) {
    int row  = blockIdx.x * 8 + (threadIdx.x >> 5);
    int lane = threadIdx.x & 31;
    const float4* xr = reinterpret_cast<const float4*>(x + (size_t)row * CC);
    float s = 0.f;
#pragma unroll
    for (int c = 0; c < 2; c++) {
        float4 v = xr[lane + 32*c];
        s += v.x*v.x + v.y*v.y + v.z*v.z + v.w*v.w;
    }
#pragma unroll
    for (int o = 16; o; o >>= 1) s += __shfl_xor_sync(0xffffffffu, s, o);
    if (lane == 0) g_sq[row] = s;
}

// ---------------- single-pass tf32 mma.sync gram -> fp32 distance tiles ----------------
// Triangular grid: blockIdx.x in [0,528) enumerates (by<=bx) pairs; blockIdx.y = batch.
// 3-buffer cp.async rotation, ONE barrier per chunk.
#define GRAM_SMEM_BYTES (98304 + 1024)
__global__ __launch_bounds__(256, 2)
void gram_mma_kernel() {
    int t = blockIdx.x, bz = blockIdx.y;
    int by = 0;
    while (t >= 32 - by) { t -= 32 - by; by++; }
    int bx = by + t;

    extern __shared__ char smem[];
    uint32_t sb = smem_u32(smem);
    float* sc    = reinterpret_cast<float*>(smem);
    float* sqi_s = reinterpret_cast<float*>(smem + 98304);
    float* sqj_s = sqi_s + 128;

    int tid = threadIdx.x;
    int wid = tid >> 5, lane = tid & 31;
    int wi = wid >> 1, wj = wid & 1;
    int gid = lane >> 2, tig = lane & 3;

    if (tid < 128) sqi_s[tid] = g_sq[bz*NN + by*128 + tid];
    else           sqj_s[tid-128] = g_sq[bz*NN + bx*128 + (tid-128)];

    float acc[2][8][4];
#pragma unroll
    for (int m = 0; m < 2; m++)
#pragma unroll
        for (int n = 0; n < 8; n++)
#pragma unroll
            for (int r = 0; r < 4; r++) acc[m][n][r] = 0.f;

    const float4* xap = reinterpret_cast<const float4*>(g_xa);
    const float4* xbp = reinterpret_cast<const float4*>(g_xb);
    size_t rbbase = (size_t)bz*256 + (size_t)by*8;
    size_t nbbase = (size_t)bz*512 + (size_t)bx*16;

    const uint32_t aoff[3] = {0u, 16384u, 32768u};
    const uint32_t boff[3] = {49152u, 65536u, 81920u};

    auto stage = [&](int c) {
        int k8b = c*4;
        int bsel = c % 3;
#pragma unroll
        for (int p = 0; p < 4; p++) {
            int o4 = tid + p*256;
            int rb = o4 >> 7, rem = o4 & 127;
            int k8l = rem >> 5, e4 = rem & 31;
            CP_ASYNC16(sb + aoff[bsel] + o4*16,
                       xap + ((rbbase + rb)*32 + k8b + k8l)*32 + e4);
            int nb = o4 >> 6, rem2 = o4 & 63;
            int k8m = rem2 >> 4, e42 = rem2 & 15;
            CP_ASYNC16(sb + boff[bsel] + o4*16,
                       xbp + ((nbbase + nb)*32 + k8b + k8m)*16 + e42);
        }
        CP_COMMIT();
    };

    stage(0); stage(1);
    for (int c = 0; c < 8; c++) {
        if (c < 7) { CP_WAIT(1); } else { CP_WAIT(0); }
        __syncthreads();          // chunk c visible to all; all done MMA-reading buf (c-1)%3
        if (c < 6) stage(c + 2);  // writes buf (c+2)%3 == (c-1)%3, safe after barrier
        int bsel = c % 3;
#pragma unroll
        for (int k8l = 0; k8l < 4; k8l++) {
            uint4 af[2]; uint2 bf[8];
#pragma unroll
            for (int m = 0; m < 2; m++)
                af[m] = *reinterpret_cast<const uint4*>(
                    smem + aoff[bsel] + (((wi*2 + m)*4 + k8l)*32 + lane)*16);
#pragma unroll
            for (int n = 0; n < 8; n++)
                bf[n] = *reinterpret_cast<const uint2*>(
                    smem + boff[bsel] + (((wj*8 + n)*4 + k8l)*32 + lane)*8);
#pragma unroll
            for (int m = 0; m < 2; m++)
#pragma unroll
                for (int n = 0; n < 8; n++)
                    MMA_TF32(acc[m][n], af[m], bf[n]);
        }
    }
    __syncthreads();              // all MMA reads done before sc reuse

#pragma unroll
    for (int m = 0; m < 2; m++) {
#pragma unroll
        for (int n = 0; n < 8; n++) {
            int row = wi*32 + m*16 + gid;
            int col = wj*64 + n*8 + 2*tig;
            *reinterpret_cast<float2*>(&sc[row*132 + col]) =
                make_float2(acc[m][n][0], acc[m][n][1]);
            *reinterpret_cast<float2*>(&sc[(row + 8)*132 + col]) =
                make_float2(acc[m][n][2], acc[m][n][3]);
        }
    }
    __syncthreads();

    float* d2b = g_d2 + (size_t)bz * NN * NN;
    const float FINF = __int_as_float(0x7f800000);
#pragma unroll
    for (int p = 0; p < 16; p++) {
        int o = tid + p*256;
        int row = o >> 5, c4 = o & 31;
        float4 v = *reinterpret_cast<float4*>(&sc[row*132 + c4*4]);
        int gi = by*128 + row, gjb = bx*128 + c4*4;
        float si = sqi_s[row];
        float4 d;
        d.x = si + sqj_s[c4*4+0] - 2.f*v.x;
        d.y = si + sqj_s[c4*4+1] - 2.f*v.y;
        d.z = si + sqj_s[c4*4+2] - 2.f*v.z;
        d.w = si + sqj_s[c4*4+3] - 2.f*v.w;
        if (gi == gjb+0) d.x = FINF;
        if (gi == gjb+1) d.y = FINF;
        if (gi == gjb+2) d.z = FINF;
        if (gi == gjb+3) d.w = FINF;
        *reinterpret_cast<float4*>(d2b + (size_t)gi*NN + gjb) = d;
    }
    if (bx != by) {
#pragma unroll
        for (int p = 0; p < 16; p++) {
            int o = tid + p*256;
            int mr = o >> 5, q4 = o & 31;
            float sj = sqj_s[mr];
            float4 d;
            d.x = sqi_s[q4*4+0] + sj - 2.f*sc[(q4*4+0)*132 + mr];
            d.y = sqi_s[q4*4+1] + sj - 2.f*sc[(q4*4+1)*132 + mr];
            d.z = sqi_s[q4*4+2] + sj - 2.f*sc[(q4*4+2)*132 + mr];
            d.w = sqi_s[q4*4+3] + sj - 2.f*sc[(q4*4+3)*132 + mr];
            *reinterpret_cast<float4*>(d2b + (size_t)(bx*128 + mr)*NN + by*128 + q4*4) = d;
        }
    }
}

// ---------------- qkv via 3xTF32 mma.sync: out = x @ W + b ----------------
#define QKV_SMEM_BYTES 65536
__global__ __launch_bounds__(256, 2)
void qkv_mma_kernel(const float* __restrict__ bq,
                    const float* __restrict__ bk,
                    const float* __restrict__ bv) {
    int bx = blockIdx.x, by = blockIdx.y, z = blockIdx.z;
    extern __shared__ char smem[];
    uint32_t sb = smem_u32(smem);

    int tid = threadIdx.x;
    int wid = tid >> 5, lane = tid & 31;
    int wi = wid >> 1, wj = wid & 1;
    int gid = lane >> 2, tig = lane & 3;

    const float* bias = (z == 0) ? bq : ((z == 1) ? bk : bv);
    float* outp = (z == 0) ? g_q : ((z == 1) ? g_k : g_v);

    float acc[2][8][4];
#pragma unroll
    for (int m = 0; m < 2; m++)
#pragma unroll
        for (int n = 0; n < 8; n++)
#pragma unroll
            for (int r = 0; r < 4; r++) acc[m][n][r] = 0.f;

    const float4* xah = reinterpret_cast<const float4*>(g_xa);
    const float4* xal = reinterpret_cast<const float4*>(g_xal);
    const float4* wbh = reinterpret_cast<const float4*>(g_wbh) + (size_t)z*16384;
    const float4* wbl = reinterpret_cast<const float4*>(g_wbl) + (size_t)z*16384;
    size_t rbbase = (size_t)by*8;
    size_t nbbase = (size_t)bx*16;

    const uint32_t aoff[2] = {0u, 16384u};
    const uint32_t boff[2] = {32768u, 49152u};

    auto stage = [&](int c) {
        int pass = c >> 3, kc = c & 7;
        int k8b = kc*4;
        int bsel = c & 1;
        const float4* asrc = (pass == 2) ? xal : xah;
        const float4* bsrc = (pass == 1) ? wbl : wbh;
#pragma unroll
        for (int p = 0; p < 4; p++) {
            int o4 = tid + p*256;
            int rb = o4 >> 7, rem = o4 & 127;
            int k8l = rem >> 5, e4 = rem & 31;
            CP_ASYNC16(sb + aoff[bsel] + o4*16,
                       asrc + ((rbbase + rb)*32 + k8b + k8l)*32 + e4);
            int nb = o4 >> 6, rem2 = o4 & 63;
            int k8m = rem2 >> 4, e42 = rem2 & 15;
            CP_ASYNC16(sb + boff[bsel] + o4*16,
                       bsrc + ((nbbase + nb)*32 + k8b + k8m)*16 + e42);
        }
        CP_COMMIT();
    };

    stage(0);
    for (int c = 0; c < 24; c++) {
        if (c < 23) { stage(c + 1); CP_WAIT(1); }
        else        { CP_WAIT(0); }
        __syncthreads();
        int bsel = c & 1;
#pragma unroll
        for (int k8l = 0; k8l < 4; k8l++) {
            uint4 af[2]; uint2 bf[8];
#pragma unroll
            for (int m = 0; m < 2; m++)
                af[m] = *reinterpret_cast<const uint4*>(
                    smem + aoff[bsel] + (((wi*2 + m)*4 + k8l)*32 + lane)*16);
#pragma unroll
            for (int n = 0; n < 8; n++)
                bf[n] = *reinterpret_cast<const uint2*>(
                    smem + boff[bsel] + (((wj*8 + n)*4 + k8l)*32 + lane)*8);
#pragma unroll
            for (int m = 0; m < 2; m++)
#pragma unroll
                for (int n = 0; n < 8; n++)
                    MMA_TF32(acc[m][n], af[m], bf[n]);
        }
        __syncthreads();
    }

    // epilogue: bias + direct store
#pragma unroll
    for (int m = 0; m < 2; m++) {
#pragma unroll
        for (int n = 0; n < 8; n++) {
            int row = by*128 + wi*32 + m*16 + gid;
            int col = bx*128 + wj*64 + n*8 + 2*tig;
            float2 bb = *reinterpret_cast<const float2*>(bias + col);
            *reinterpret_cast<float2*>(outp + (size_t)row*HDIM + col) =
                make_float2(acc[m][n][0] + bb.x, acc[m][n][1] + bb.y);
            *reinterpret_cast<float2*>(outp + (size_t)(row+8)*HDIM + col) =
                make_float2(acc[m][n][2] + bb.x, acc[m][n][3] + bb.y);
        }
    }
}

// ---------------- topk: threshold -> compact -> exact rerank ALL -> exact top-16 ----------------
#define TOPK_SMEM_BYTES (8 * TKCAP * 8)   // 32 KB
__global__ __launch_bounds__(256)
void topk_kernel(const float* __restrict__ x) {
    extern __shared__ unsigned long long sbuf[];
    int tid  = threadIdx.x;
    int wip  = tid >> 5, lane = tid & 31;
    unsigned long long* buf = sbuf + (size_t)wip * TKCAP;
    int row = (blockIdx.x * blockDim.x + tid) >> 5;            // 0..TOT-1
    int bz = row >> 12, ri = row & (NN-1);
    const float4* rp = reinterpret_cast<const float4*>(g_d2 + (size_t)row * NN);
    const float FINF = __int_as_float(0x7f800000);

    // ---- pass 1: per-lane top-2 of float4-minima -> warp CAND-th smallest = T ----
    float t1 = FINF, t2 = FINF;
    for (int it = 0; it < NN/128; it++) {
        float4 v = rp[it*32 + lane];
        float m = fminf(fminf(v.x, v.y), fminf(v.z, v.w));
        if (m < t2) {
            t2 = m;
            if (t2 < t1) { float tm = t1; t1 = t2; t2 = tm; }
        }
    }
    float T = FINF;
#pragma unroll
    for (int r = 0; r < CAND; r++) {
        float m = t1;
#pragma unroll
        for (int o = 16; o; o >>= 1) m = fminf(m, __shfl_xor_sync(0xffffffffu, m, o));
        if (t1 == m) { t1 = t2; t2 = FINF; }                  // kill winner(s)
        T = m;
    }

    // ---- pass 2: ballot-compact all elements <= T into per-warp buffer ----
    int cnt = 0;
    for (int it = 0; it < NN/128; it++) {
        float4 v = rp[it*32 + lane];
        int jb = (it*32 + lane) * 4;
        float dv[4] = {v.x, v.y, v.z, v.w};
#pragma unroll
        for (int c = 0; c < 4; c++) {
            bool p = (dv[c] <= T);
            unsigned msk = __ballot_sync(0xffffffffu, p);
            if (msk) {
                int off = cnt + __popc(msk & ((1u << lane) - 1u));
                if (p && off < TKCAP)
                    buf[off] = ((unsigned long long)__float_as_uint(dv[c]) << 32)
                             | (unsigned)(jb + c);
                cnt += __popc(msk);
            }
        }
    }
    if (cnt > TKCAP) cnt = TKCAP;
    __syncwarp();

    // ---- exact fp32 rerank of ALL survivors (in place) ----
    const float* xb = x + (size_t)bz * NN * CC;
    const float4* xi = reinterpret_cast<const float4*>(xb + (size_t)ri * CC);
    float4 xi0 = xi[lane*2], xi1 = xi[lane*2 + 1];
    float sqi = g_sq[row];
    for (int t = 0; t < cnt; t++) {
        int nb = (int)(buf[t] & 0xffffffffu);
        const float4* xj = reinterpret_cast<const float4*>(xb + (size_t)nb * CC);
        float4 a = xj[lane*2], b = xj[lane*2 + 1];
        float p = xi0.x*a.x + xi0.y*a.y + xi0.z*a.z + xi0.w*a.w
                + xi1.x*b.x + xi1.y*b.y + xi1.z*b.z + xi1.w*b.w;
#pragma unroll
        for (int o = 16; o; o >>= 1) p += __shfl_xor_sync(0xffffffffu, p, o);
        float d = sqi + g_sq[bz*NN + nb] - 2.f*p;
        if (lane == 0)
            buf[t] = ((unsigned long long)__float_as_uint(d) << 32) | (unsigned)nb;
    }
    __syncwarp();

    // ---- exact top-16 extraction (ascending (d, idx) = jax top_k order) ----
    const unsigned long long INFK = 0xffffffffffffffffULL;
#pragma unroll 1
    for (int r = 0; r < KNN; r++) {
        unsigned long long mymin = INFK; int myarg = -1;
        for (int i = lane; i < cnt; i += 32) {
            unsigned long long k = buf[i];
            if (k < mymin) { mymin = k; myarg = i; }
        }
        unsigned long long wk = mymin;
#pragma unroll
        for (int o = 16; o; o >>= 1) {
            unsigned long long other = __shfl_xor_sync(0xffffffffu, wk, o);
            if (other < wk) wk = other;
        }
        if (mymin == wk && myarg >= 0) buf[myarg] = INFK;   // unique key (idx embedded)
        if (lane == 0) g_nbr[(size_t)row*KNN + r] = (int)(wk & 0xffffffffu);
        __syncwarp();
    }
}

// ---------------- sparse attention: one warp per node, loop heads ----------------
__global__ void attn_kernel(float* __restrict__ out) {
    int node = (blockIdx.x * blockDim.x + threadIdx.x) >> 5;
    int lane = threadIdx.x & 31;
    int b = node >> 12;
    size_t base  = (size_t)node * HDIM;
    size_t bbase = (size_t)b * NN * HDIM;
    int nbr_l = g_nbr[(size_t)node*KNN + (lane & 15)];
    const float scale = 0.17677669529663687f;
    const float NINF = -__int_as_float(0x7f800000);

    for (int h = 0; h < NH; h++) {
        int off = h*DH + lane;
        float qd = g_q[base + off];
        float sc = 0.f;
#pragma unroll
        for (int kk = 0; kk < KNN; kk++) {
            int nb = __shfl_sync(0xffffffffu, nbr_l, kk);
            float p = qd * g_k[bbase + (size_t)nb*HDIM + off];
#pragma unroll
            for (int o = 16; o; o >>= 1) p += __shfl_xor_sync(0xffffffffu, p, o);
            if (lane == kk) sc = p * scale;
        }
        float m = (lane < 16) ? sc : NINF;
#pragma unroll
        for (int o = 16; o; o >>= 1) m = fmaxf(m, __shfl_xor_sync(0xffffffffu, m, o));
        float e = (lane < 16) ? expf(sc - m) : 0.f;
        float s = e;
#pragma unroll
        for (int o = 16; o; o >>= 1) s += __shfl_xor_sync(0xffffffffu, s, o);
        float alpha = e / s;
        float acc = 0.f;
#pragma unroll
        for (int kk = 0; kk < KNN; kk++) {
            float a = __shfl_sync(0xffffffffu, alpha, kk);
            int nb  = __shfl_sync(0xffffffffu, nbr_l, kk);
            acc += a * g_v[bbase + (size_t)nb*HDIM + off];
        }
        out[base + off] = acc;
    }
}

// ---------------- launch ----------------
extern "C" void kernel_launch(void* const* d_in, const int* in_sizes, int n_in,
                              void* d_out, int out_size) {
    const float* x  = (const float*)d_in[0];
    const float* Wq = (const float*)d_in[1];
    const float* bq = (const float*)d_in[2];
    const float* Wk = (const float*)d_in[3];
    const float* bk = (const float*)d_in[4];
    const float* Wv = (const float*)d_in[5];
    const float* bv = (const float*)d_in[6];
    float* out = (float*)d_out;

    cudaFuncSetAttribute(gram_mma_kernel,
                         cudaFuncAttributeMaxDynamicSharedMemorySize, GRAM_SMEM_BYTES);
    cudaFuncSetAttribute(qkv_mma_kernel,
                         cudaFuncAttributeMaxDynamicSharedMemorySize, QKV_SMEM_BYTES);
    cudaFuncSetAttribute(topk_kernel,
                         cudaFuncAttributeMaxDynamicSharedMemorySize, TOPK_SMEM_BYTES);

    decomp_kernel<<<TOT/16, 256>>>(x);
    wdecomp_kernel<<<dim3(256, 3), 256>>>(Wq, Wk, Wv);
    norms_kernel<<<TOT/8, 256>>>(x);
    gram_mma_kernel<<<dim3(528, NB), 256, GRAM_SMEM_BYTES>>>();
    topk_kernel<<<TOT/8, 256, TOPK_SMEM_BYTES>>>(x);
    qkv_mma_kernel<<<dim3(2, TOT/128, 3), 256, QKV_SMEM_BYTES>>>(bq, bk, bv);
    attn_kernel<<<TOT/8, 256>>>(out);
}